// round 6
// baseline (speedup 1.0000x reference)
#include <cuda_runtime.h>
#include <cstddef>

// ---------------------------------------------------------------------------
// CrossAttention: out = softmax((xWq)(ctxWk)^T * D^-0.5) (ctxWv) Wo + bo
// B=4, N=4096, M=1024, QUERY_DIM=1024, CONTEXT_DIM=768, H=16, D=64, INNER=1024
// ---------------------------------------------------------------------------

#define BATCH      4
#define SEQ_N      4096
#define SEQ_M      1024
#define QDIM       1024
#define CDIM       768
#define HEADS      16
#define DHEAD      64
#define INNER      1024
#define ROWS_Q     (BATCH * SEQ_N)   // 16384
#define ROWS_KV    (BATCH * SEQ_M)   // 4096

// Scratch (static device globals — no allocation at runtime)
__device__ float g_Q[(size_t)ROWS_Q  * INNER];            // 64 MB
__device__ float g_K[(size_t)ROWS_KV * INNER];            // 16 MB
__device__ float g_V[(size_t)ROWS_KV * INNER];            // 16 MB
__device__ float g_S[(size_t)BATCH * HEADS * SEQ_N * SEQ_M]; // 1 GB scores
__device__ float g_O[(size_t)ROWS_Q  * INNER];            // 64 MB

// ---------------------------------------------------------------------------
// Generic register-blocked SGEMM with double-buffered smem pipeline.
//   C[M,N] = A[M,K] * B[K,N]          (TRANSB = false)
//   C[M,N] = A[M,K] * B[N,K]^T        (TRANSB = true)
// Batched over blockIdx.z with two-level offsets:
//   zb = z / zdiv, zh = z % zdiv;  ptr += zb*s1 + zh*s2
// Grid must exactly tile (M/BM, N/BN). All dims divisible by tiles here.
// ---------------------------------------------------------------------------
template<int BM, int BN, int BK, int TM, int TN, bool TRANSB, bool BIAS>
__global__ void gemm_kernel(const float* __restrict__ A,
                            const float* __restrict__ B,
                            float* __restrict__ C,
                            const float* __restrict__ bias,
                            int K, int lda, int ldb, int ldc,
                            int zdiv,
                            size_t sA1, size_t sA2,
                            size_t sB1, size_t sB2,
                            size_t sC1, size_t sC2)
{
    constexpr int THREADS = (BM / TM) * (BN / TN);
    constexpr int A_ITERS = (BM * BK / 4) / THREADS;
    constexpr int B_ITERS = (BK * BN / 4) / THREADS;
    static_assert((BM * BK / 4) % THREADS == 0, "A tile load");
    static_assert((BK * BN / 4) % THREADS == 0, "B tile load");
    static_assert(TM % 4 == 0 && TN % 4 == 0, "vec epilogue");
    static_assert(BK % 4 == 0, "vec k");

    __shared__ float AsT[2][BK][BM];   // K-major (transposed) A tiles
    __shared__ float Bs [2][BK][BN];   // K-major B tiles

    const int z  = blockIdx.z;
    const int zb = z / zdiv;
    const int zh = z % zdiv;
    const float* Ab = A + zb * sA1 + zh * sA2;
    const float* Bb = B + zb * sB1 + zh * sB2;
    float*       Cb = C + zb * sC1 + zh * sC2;

    const int tid  = threadIdx.x;
    const int tx   = tid % (BN / TN);
    const int ty   = tid / (BN / TN);
    const int row0 = blockIdx.y * BM;
    const int col0 = blockIdx.x * BN;

    float4 aReg[A_ITERS];
    float4 bReg[B_ITERS];

    // ---- global -> register staging ----
    auto loadA = [&](int k0) {
#pragma unroll
        for (int i = 0; i < A_ITERS; i++) {
            int v   = tid + i * THREADS;
            int r   = v / (BK / 4);
            int kk4 = v % (BK / 4);
            aReg[i] = *reinterpret_cast<const float4*>(
                &Ab[(size_t)(row0 + r) * lda + k0 + kk4 * 4]);
        }
    };
    auto loadB = [&](int k0) {
        if (!TRANSB) {
#pragma unroll
            for (int i = 0; i < B_ITERS; i++) {
                int v  = tid + i * THREADS;
                int kk = v / (BN / 4);
                int c4 = v % (BN / 4);
                bReg[i] = *reinterpret_cast<const float4*>(
                    &Bb[(size_t)(k0 + kk) * ldb + col0 + c4 * 4]);
            }
        } else {
#pragma unroll
            for (int i = 0; i < B_ITERS; i++) {
                int v   = tid + i * THREADS;
                int j   = v / (BK / 4);
                int kk4 = v % (BK / 4);
                bReg[i] = *reinterpret_cast<const float4*>(
                    &Bb[(size_t)(col0 + j) * ldb + k0 + kk4 * 4]);
            }
        }
    };
    // ---- register -> shared commit ----
    auto storeA = [&](int buf) {
#pragma unroll
        for (int i = 0; i < A_ITERS; i++) {
            int v   = tid + i * THREADS;
            int r   = v / (BK / 4);
            int kk4 = v % (BK / 4);
            AsT[buf][kk4 * 4 + 0][r] = aReg[i].x;
            AsT[buf][kk4 * 4 + 1][r] = aReg[i].y;
            AsT[buf][kk4 * 4 + 2][r] = aReg[i].z;
            AsT[buf][kk4 * 4 + 3][r] = aReg[i].w;
        }
    };
    auto storeB = [&](int buf) {
        if (!TRANSB) {
#pragma unroll
            for (int i = 0; i < B_ITERS; i++) {
                int v  = tid + i * THREADS;
                int kk = v / (BN / 4);
                int c4 = v % (BN / 4);
                *reinterpret_cast<float4*>(&Bs[buf][kk][c4 * 4]) = bReg[i];
            }
        } else {
#pragma unroll
            for (int i = 0; i < B_ITERS; i++) {
                int v   = tid + i * THREADS;
                int j   = v / (BK / 4);
                int kk4 = v % (BK / 4);
                Bs[buf][kk4 * 4 + 0][j] = bReg[i].x;
                Bs[buf][kk4 * 4 + 1][j] = bReg[i].y;
                Bs[buf][kk4 * 4 + 2][j] = bReg[i].z;
                Bs[buf][kk4 * 4 + 3][j] = bReg[i].w;
            }
        }
    };

    float acc[TM][TN];
#pragma unroll
    for (int r = 0; r < TM; r++)
#pragma unroll
        for (int c = 0; c < TN; c++) acc[r][c] = 0.f;

    const int nT = K / BK;
    loadA(0); loadB(0);
    storeA(0); storeB(0);
    __syncthreads();

    for (int t = 0; t < nT; t++) {
        const int cur = t & 1;
        // prefetch next tile into registers (overlaps with FMA block below)
        if (t + 1 < nT) { loadA((t + 1) * BK); loadB((t + 1) * BK); }

        // ---- compute from buffer `cur` ----
#pragma unroll
        for (int kk = 0; kk < BK; kk++) {
            float a[TM], b[TN];
#pragma unroll
            for (int r = 0; r < TM; r += 4) {
                float4 v = *reinterpret_cast<const float4*>(&AsT[cur][kk][ty * TM + r]);
                a[r + 0] = v.x; a[r + 1] = v.y; a[r + 2] = v.z; a[r + 3] = v.w;
            }
#pragma unroll
            for (int c = 0; c < TN; c += 4) {
                float4 v = *reinterpret_cast<const float4*>(&Bs[cur][kk][tx * TN + c]);
                b[c + 0] = v.x; b[c + 1] = v.y; b[c + 2] = v.z; b[c + 3] = v.w;
            }
#pragma unroll
            for (int r = 0; r < TM; r++)
#pragma unroll
                for (int c = 0; c < TN; c++)
                    acc[r][c] = fmaf(a[r], b[c], acc[r][c]);
        }

        // commit prefetched tile into the other buffer (safe: its last readers
        // finished before the sync that ended iteration t-1)
        if (t + 1 < nT) { storeA(cur ^ 1); storeB(cur ^ 1); }
        __syncthreads();
    }

    // ---- epilogue ----
#pragma unroll
    for (int r = 0; r < TM; r++) {
        size_t crow = (size_t)(row0 + ty * TM + r) * ldc;
#pragma unroll
        for (int c = 0; c < TN; c += 4) {
            int col = col0 + tx * TN + c;
            float4 v;
            v.x = acc[r][c + 0];
            v.y = acc[r][c + 1];
            v.z = acc[r][c + 2];
            v.w = acc[r][c + 3];
            if (BIAS) {
                v.x += bias[col + 0];
                v.y += bias[col + 1];
                v.z += bias[col + 2];
                v.w += bias[col + 3];
            }
            *reinterpret_cast<float4*>(&Cb[crow + col]) = v;
        }
    }
}

// ---------------------------------------------------------------------------
// Row softmax over 1024 columns (in place), with pre-scale.
// One block (256 threads) per row, 4 elements per thread.
// ---------------------------------------------------------------------------
__global__ void softmax_kernel(float* __restrict__ S, float scale)
{
    constexpr int VPT  = 4;
    size_t row = blockIdx.x;
    float* p = S + row * 1024;
    int t = threadIdx.x;

    float v[VPT];
    float mx = -3.4e38f;
#pragma unroll
    for (int i = 0; i < VPT; i++) {
        v[i] = p[t + i * 256] * scale;
        mx = fmaxf(mx, v[i]);
    }

    __shared__ float red[8];
#pragma unroll
    for (int o = 16; o > 0; o >>= 1)
        mx = fmaxf(mx, __shfl_xor_sync(0xffffffffu, mx, o));
    if ((t & 31) == 0) red[t >> 5] = mx;
    __syncthreads();
    mx = red[0];
#pragma unroll
    for (int i = 1; i < 8; i++) mx = fmaxf(mx, red[i]);

    float sum = 0.f;
#pragma unroll
    for (int i = 0; i < VPT; i++) {
        v[i] = __expf(v[i] - mx);
        sum += v[i];
    }
#pragma unroll
    for (int o = 16; o > 0; o >>= 1)
        sum += __shfl_xor_sync(0xffffffffu, sum, o);
    __syncthreads();                 // all reads of red[] done
    if ((t & 31) == 0) red[t >> 5] = sum;
    __syncthreads();
    sum = 0.f;
#pragma unroll
    for (int i = 0; i < 8; i++) sum += red[i];

    float inv = 1.f / sum;
#pragma unroll
    for (int i = 0; i < VPT; i++) p[t + i * 256] = v[i] * inv;
}

// ---------------------------------------------------------------------------
extern "C" void kernel_launch(void* const* d_in, const int* in_sizes, int n_in,
                              void* d_out, int out_size)
{
    const float* x   = (const float*)d_in[0];  // [4,4096,1024]
    const float* ctx = (const float*)d_in[1];  // [4,1024,768]
    const float* Wq  = (const float*)d_in[2];  // [1024,1024]
    const float* Wk  = (const float*)d_in[3];  // [768,1024]
    const float* Wv  = (const float*)d_in[4];  // [768,1024]
    const float* Wo  = (const float*)d_in[5];  // [1024,1024]
    const float* bo  = (const float*)d_in[6];  // [1024]
    float* out = (float*)d_out;                // [4,4096,1024]

    float *Q, *Kb, *V, *S, *O;
    cudaGetSymbolAddress((void**)&Q,  g_Q);
    cudaGetSymbolAddress((void**)&Kb, g_K);
    cudaGetSymbolAddress((void**)&V,  g_V);
    cudaGetSymbolAddress((void**)&S,  g_S);
    cudaGetSymbolAddress((void**)&O,  g_O);

    const size_t SNM = (size_t)SEQ_N * SEQ_M;  // 4096*1024 per (b,h) score slab

    // 1) Q = x @ Wq          [16384,1024] x [1024,1024]
    gemm_kernel<128,128,16,8,8,false,false>
        <<<dim3(INNER/128, ROWS_Q/128, 1), 256>>>(
            x, Wq, Q, nullptr, QDIM, QDIM, INNER, INNER,
            1, 0,0, 0,0, 0,0);

    // 2) K = ctx @ Wk        [4096,768] x [768,1024]
    gemm_kernel<128,128,16,8,8,false,false>
        <<<dim3(INNER/128, ROWS_KV/128, 1), 256>>>(
            ctx, Wk, Kb, nullptr, CDIM, CDIM, INNER, INNER,
            1, 0,0, 0,0, 0,0);

    // 3) V = ctx @ Wv
    gemm_kernel<128,128,16,8,8,false,false>
        <<<dim3(INNER/128, ROWS_KV/128, 1), 256>>>(
            ctx, Wv, V, nullptr, CDIM, CDIM, INNER, INNER,
            1, 0,0, 0,0, 0,0);

    // 4) S[b,h] = Q[b,:,h,:] @ K[b,:,h,:]^T    [4096,64] x [1024,64]^T
    gemm_kernel<128,128,16,8,8,true,false>
        <<<dim3(SEQ_M/128, SEQ_N/128, BATCH*HEADS), 256>>>(
            Q, Kb, S, nullptr, DHEAD, INNER, INNER, SEQ_M,
            HEADS,
            (size_t)SEQ_N * INNER, (size_t)DHEAD,   // A: b-stride, h-stride
            (size_t)SEQ_M * INNER, (size_t)DHEAD,   // B
            (size_t)HEADS * SNM,   SNM);            // C

    // 5) softmax rows of S, scale = 1/sqrt(64)
    softmax_kernel<<<(unsigned)((size_t)BATCH * HEADS * SEQ_N), 256>>>(S, 0.125f);

    // 6) O[b,:,h,:] = P[b,h] @ V[b,:,h,:]      [4096,1024] x [1024,64]
    gemm_kernel<128,64,16,8,4,false,false>
        <<<dim3(DHEAD/64, SEQ_N/128, BATCH*HEADS), 256>>>(
            S, V, O, nullptr, SEQ_M, SEQ_M, INNER, INNER,
            HEADS,
            (size_t)HEADS * SNM,   SNM,             // A (scores)
            (size_t)SEQ_M * INNER, (size_t)DHEAD,   // B (V)
            (size_t)SEQ_N * INNER, (size_t)DHEAD);  // C (O)

    // 7) out = O @ Wo + bo   [16384,1024] x [1024,1024]
    gemm_kernel<128,128,16,8,8,false,true>
        <<<dim3(INNER/128, ROWS_Q/128, 1), 256>>>(
            O, Wo, out, bo, INNER, INNER, QDIM, QDIM,
            1, 0,0, 0,0, 0,0);
}

// round 7
// speedup vs baseline: 1.1192x; 1.1192x over previous
#include <cuda_runtime.h>
#include <cstddef>
#include <cstdint>

// ---------------------------------------------------------------------------
// CrossAttention: out = softmax((xWq)(ctxWk)^T * D^-0.5) (ctxWv) Wo + bo
// B=4, N=4096, M=1024, QUERY_DIM=1024, CONTEXT_DIM=768, H=16, D=64, INNER=1024
// GEMMs on tensor cores via mma.sync tf32 with 3xTF32 split (fp32 accuracy).
// ---------------------------------------------------------------------------

#define BATCH      4
#define SEQ_N      4096
#define SEQ_M      1024
#define QDIM       1024
#define CDIM       768
#define HEADS      16
#define DHEAD      64
#define INNER      1024
#define ROWS_Q     (BATCH * SEQ_N)   // 16384
#define ROWS_KV    (BATCH * SEQ_M)   // 4096

// Scratch (static device globals — no allocation at runtime)
__device__ float g_Q[(size_t)ROWS_Q  * INNER];
__device__ float g_K[(size_t)ROWS_KV * INNER];
__device__ float g_V[(size_t)ROWS_KV * INNER];
__device__ float g_S[(size_t)BATCH * HEADS * SEQ_N * SEQ_M]; // 1 GB scores
__device__ float g_O[(size_t)ROWS_Q  * INNER];

// ---------------------------------------------------------------------------
// helpers
// ---------------------------------------------------------------------------
__device__ __forceinline__ float tf32r(float x) {
    uint32_t u;
    asm("cvt.rna.tf32.f32 %0, %1;" : "=r"(u) : "f"(x));
    return __uint_as_float(u);
}

__device__ __forceinline__ void mma_tf32(float* c, const uint32_t* a, const uint32_t* b) {
    asm volatile(
        "mma.sync.aligned.m16n8k8.row.col.f32.tf32.tf32.f32 "
        "{%0,%1,%2,%3}, {%4,%5,%6,%7}, {%8,%9}, {%0,%1,%2,%3};"
        : "+f"(c[0]), "+f"(c[1]), "+f"(c[2]), "+f"(c[3])
        : "r"(a[0]), "r"(a[1]), "r"(a[2]), "r"(a[3]),
          "r"(b[0]), "r"(b[1]));
}

// ---------------------------------------------------------------------------
// Tensor-core GEMM (tf32 x3 split, fp32 accumulate).
//   C[M,N] = A[M,K] * B[K,N]          (TRANSB = false)
//   C[M,N] = A[M,K] * B[N,K]^T        (TRANSB = true)
// Batched over blockIdx.z: zb = z/zdiv, zh = z%zdiv; ptr += zb*s1 + zh*s2.
// Warp tile WM x WN, mma m16n8k8 fragments. K % BK == 0, BK % 8 == 0.
// ---------------------------------------------------------------------------
template<int BM, int BN, int BK, int WM, int WN, bool TRANSB, bool BIAS>
__global__ void mma_gemm(const float* __restrict__ A,
                         const float* __restrict__ B,
                         float* __restrict__ C,
                         const float* __restrict__ bias,
                         int K, int lda, int ldb, int ldc,
                         int zdiv,
                         size_t sA1, size_t sA2,
                         size_t sB1, size_t sB2,
                         size_t sC1, size_t sC2)
{
    constexpr int WARPS_M = BM / WM;
    constexpr int WARPS_N = BN / WN;
    constexpr int THREADS = WARPS_M * WARPS_N * 32;
    constexpr int MF = WM / 16;            // m fragments per warp
    constexpr int NF = WN / 8;             // n fragments per warp
    constexpr int NC = (NF >= 4) ? 4 : NF; // n-frag chunk (register control)
    constexpr int SA = BM + 8;             // pad: stride%32==8 -> conflict-free frags
    constexpr int SB = BN + 8;
    constexpr int A_IT = (BM * BK / 4) / THREADS;
    constexpr int B_IT = (BK * BN / 4) / THREADS;
    static_assert((BM * BK / 4) % THREADS == 0, "A tile");
    static_assert((BK * BN / 4) % THREADS == 0, "B tile");
    static_assert(BK % 8 == 0 && WM % 16 == 0 && WN % 8 == 0 && NF % NC == 0, "tiles");

    __shared__ float As_hi[BK][SA], As_lo[BK][SA];
    __shared__ float Bs_hi[BK][SB], Bs_lo[BK][SB];

    const int z  = blockIdx.z;
    const int zb = z / zdiv;
    const int zh = z % zdiv;
    const float* Ab = A + zb * sA1 + zh * sA2;
    const float* Bb = B + zb * sB1 + zh * sB2;
    float*       Cb = C + zb * sC1 + zh * sC2;

    const int tid  = threadIdx.x;
    const int wid  = tid >> 5;
    const int lane = tid & 31;
    const int gid  = lane >> 2;   // groupID (0..7)
    const int tig  = lane & 3;    // thread-in-group (0..3)
    const int wm   = wid % WARPS_M;
    const int wn   = wid / WARPS_M;
    const int row0 = blockIdx.y * BM;
    const int col0 = blockIdx.x * BN;

    float4 aReg[A_IT], bReg[B_IT];

    auto loadA = [&](int k0) {
#pragma unroll
        for (int i = 0; i < A_IT; i++) {
            int v   = tid + i * THREADS;
            int r   = v / (BK / 4);
            int kk4 = v % (BK / 4);
            aReg[i] = *reinterpret_cast<const float4*>(
                &Ab[(size_t)(row0 + r) * lda + k0 + kk4 * 4]);
        }
    };
    auto loadB = [&](int k0) {
        if (!TRANSB) {
#pragma unroll
            for (int i = 0; i < B_IT; i++) {
                int v  = tid + i * THREADS;
                int kk = v / (BN / 4);
                int c4 = v % (BN / 4);
                bReg[i] = *reinterpret_cast<const float4*>(
                    &Bb[(size_t)(k0 + kk) * ldb + col0 + c4 * 4]);
            }
        } else {
#pragma unroll
            for (int i = 0; i < B_IT; i++) {
                int v   = tid + i * THREADS;
                int j   = v / (BK / 4);
                int kk4 = v % (BK / 4);
                bReg[i] = *reinterpret_cast<const float4*>(
                    &Bb[(size_t)(col0 + j) * ldb + k0 + kk4 * 4]);
            }
        }
    };
    // commit staged regs into hi/lo tf32 tiles (A transposed to K-major)
    auto storeTiles = [&]() {
#pragma unroll
        for (int i = 0; i < A_IT; i++) {
            int v   = tid + i * THREADS;
            int r   = v / (BK / 4);
            int kk4 = v % (BK / 4);
            float e[4] = {aReg[i].x, aReg[i].y, aReg[i].z, aReg[i].w};
#pragma unroll
            for (int q = 0; q < 4; q++) {
                float h = tf32r(e[q]);
                As_hi[kk4 * 4 + q][r] = h;
                As_lo[kk4 * 4 + q][r] = tf32r(e[q] - h);
            }
        }
        if (!TRANSB) {
#pragma unroll
            for (int i = 0; i < B_IT; i++) {
                int v  = tid + i * THREADS;
                int kk = v / (BN / 4);
                int c4 = v % (BN / 4);
                float e[4] = {bReg[i].x, bReg[i].y, bReg[i].z, bReg[i].w};
#pragma unroll
                for (int q = 0; q < 4; q++) {
                    float h = tf32r(e[q]);
                    Bs_hi[kk][c4 * 4 + q] = h;
                    Bs_lo[kk][c4 * 4 + q] = tf32r(e[q] - h);
                }
            }
        } else {
#pragma unroll
            for (int i = 0; i < B_IT; i++) {
                int v   = tid + i * THREADS;
                int j   = v / (BK / 4);
                int kk4 = v % (BK / 4);
                float e[4] = {bReg[i].x, bReg[i].y, bReg[i].z, bReg[i].w};
#pragma unroll
                for (int q = 0; q < 4; q++) {
                    float h = tf32r(e[q]);
                    Bs_hi[kk4 * 4 + q][j] = h;
                    Bs_lo[kk4 * 4 + q][j] = tf32r(e[q] - h);
                }
            }
        }
    };

    float acc[MF][NF][4];
#pragma unroll
    for (int mi = 0; mi < MF; mi++)
#pragma unroll
        for (int ni = 0; ni < NF; ni++)
#pragma unroll
            for (int q = 0; q < 4; q++) acc[mi][ni][q] = 0.f;

    const int nT = K / BK;
    loadA(0); loadB(0);

    for (int t = 0; t < nT; t++) {
        storeTiles();
        __syncthreads();
        if (t + 1 < nT) { loadA((t + 1) * BK); loadB((t + 1) * BK); }  // overlaps MMA

#pragma unroll
        for (int ks = 0; ks < BK / 8; ks++) {
            const int k0 = ks * 8;
            uint32_t ah[MF][4], al[MF][4];
#pragma unroll
            for (int mi = 0; mi < MF; mi++) {
                int m = wm * WM + mi * 16;
                ah[mi][0] = __float_as_uint(As_hi[k0 + tig    ][m + gid    ]);
                ah[mi][1] = __float_as_uint(As_hi[k0 + tig    ][m + gid + 8]);
                ah[mi][2] = __float_as_uint(As_hi[k0 + tig + 4][m + gid    ]);
                ah[mi][3] = __float_as_uint(As_hi[k0 + tig + 4][m + gid + 8]);
                al[mi][0] = __float_as_uint(As_lo[k0 + tig    ][m + gid    ]);
                al[mi][1] = __float_as_uint(As_lo[k0 + tig    ][m + gid + 8]);
                al[mi][2] = __float_as_uint(As_lo[k0 + tig + 4][m + gid    ]);
                al[mi][3] = __float_as_uint(As_lo[k0 + tig + 4][m + gid + 8]);
            }
#pragma unroll
            for (int nc = 0; nc < NF / NC; nc++) {
                uint32_t bh[NC][2], bl[NC][2];
#pragma unroll
                for (int nj = 0; nj < NC; nj++) {
                    int n = wn * WN + (nc * NC + nj) * 8 + gid;
                    bh[nj][0] = __float_as_uint(Bs_hi[k0 + tig    ][n]);
                    bh[nj][1] = __float_as_uint(Bs_hi[k0 + tig + 4][n]);
                    bl[nj][0] = __float_as_uint(Bs_lo[k0 + tig    ][n]);
                    bl[nj][1] = __float_as_uint(Bs_lo[k0 + tig + 4][n]);
                }
#pragma unroll
                for (int mi = 0; mi < MF; mi++)
#pragma unroll
                    for (int nj = 0; nj < NC; nj++) {
                        float* c = acc[mi][nc * NC + nj];
                        mma_tf32(c, ah[mi], bh[nj]);   // hi*hi
                        mma_tf32(c, ah[mi], bl[nj]);   // hi*lo
                        mma_tf32(c, al[mi], bh[nj]);   // lo*hi
                    }
            }
        }
        __syncthreads();
    }

    // ---- epilogue ----
#pragma unroll
    for (int mi = 0; mi < MF; mi++) {
        int r = row0 + wm * WM + mi * 16 + gid;
#pragma unroll
        for (int ni = 0; ni < NF; ni++) {
            int c = col0 + wn * WN + ni * 8 + tig * 2;
            float2 v01, v23;
            v01.x = acc[mi][ni][0]; v01.y = acc[mi][ni][1];
            v23.x = acc[mi][ni][2]; v23.y = acc[mi][ni][3];
            if (BIAS) {
                float b0 = bias[c], b1 = bias[c + 1];
                v01.x += b0; v01.y += b1;
                v23.x += b0; v23.y += b1;
            }
            *reinterpret_cast<float2*>(&Cb[(size_t)r * ldc + c])       = v01;
            *reinterpret_cast<float2*>(&Cb[(size_t)(r + 8) * ldc + c]) = v23;
        }
    }
}

// ---------------------------------------------------------------------------
// Row softmax over 1024 columns (in place), with pre-scale.
// ---------------------------------------------------------------------------
__global__ void softmax_kernel(float* __restrict__ S, float scale)
{
    constexpr int VPT = 4;
    size_t row = blockIdx.x;
    float* p = S + row * 1024;
    int t = threadIdx.x;

    float v[VPT];
    float mx = -3.4e38f;
#pragma unroll
    for (int i = 0; i < VPT; i++) {
        v[i] = p[t + i * 256] * scale;
        mx = fmaxf(mx, v[i]);
    }

    __shared__ float red[8];
#pragma unroll
    for (int o = 16; o > 0; o >>= 1)
        mx = fmaxf(mx, __shfl_xor_sync(0xffffffffu, mx, o));
    if ((t & 31) == 0) red[t >> 5] = mx;
    __syncthreads();
    mx = red[0];
#pragma unroll
    for (int i = 1; i < 8; i++) mx = fmaxf(mx, red[i]);

    float sum = 0.f;
#pragma unroll
    for (int i = 0; i < VPT; i++) {
        v[i] = __expf(v[i] - mx);
        sum += v[i];
    }
#pragma unroll
    for (int o = 16; o > 0; o >>= 1)
        sum += __shfl_xor_sync(0xffffffffu, sum, o);
    __syncthreads();
    if ((t & 31) == 0) red[t >> 5] = sum;
    __syncthreads();
    sum = 0.f;
#pragma unroll
    for (int i = 0; i < 8; i++) sum += red[i];

    float inv = 1.f / sum;
#pragma unroll
    for (int i = 0; i < VPT; i++) p[t + i * 256] = v[i] * inv;
}

// ---------------------------------------------------------------------------
extern "C" void kernel_launch(void* const* d_in, const int* in_sizes, int n_in,
                              void* d_out, int out_size)
{
    const float* x   = (const float*)d_in[0];  // [4,4096,1024]
    const float* ctx = (const float*)d_in[1];  // [4,1024,768]
    const float* Wq  = (const float*)d_in[2];  // [1024,1024]
    const float* Wk  = (const float*)d_in[3];  // [768,1024]
    const float* Wv  = (const float*)d_in[4];  // [768,1024]
    const float* Wo  = (const float*)d_in[5];  // [1024,1024]
    const float* bo  = (const float*)d_in[6];  // [1024]
    float* out = (float*)d_out;                // [4,4096,1024]

    float *Q, *Kb, *V, *S, *O;
    cudaGetSymbolAddress((void**)&Q,  g_Q);
    cudaGetSymbolAddress((void**)&Kb, g_K);
    cudaGetSymbolAddress((void**)&V,  g_V);
    cudaGetSymbolAddress((void**)&S,  g_S);
    cudaGetSymbolAddress((void**)&O,  g_O);

    const size_t SNM = (size_t)SEQ_N * SEQ_M;

    // 1) Q = x @ Wq          [16384,1024] x [1024,1024]
    mma_gemm<128,128,16,32,64,false,false>
        <<<dim3(INNER/128, ROWS_Q/128, 1), 256>>>(
            x, Wq, Q, nullptr, QDIM, QDIM, INNER, INNER,
            1, 0,0, 0,0, 0,0);

    // 2) K = ctx @ Wk        [4096,768] x [768,1024]
    mma_gemm<128,128,16,32,64,false,false>
        <<<dim3(INNER/128, ROWS_KV/128, 1), 256>>>(
            ctx, Wk, Kb, nullptr, CDIM, CDIM, INNER, INNER,
            1, 0,0, 0,0, 0,0);

    // 3) V = ctx @ Wv
    mma_gemm<128,128,16,32,64,false,false>
        <<<dim3(INNER/128, ROWS_KV/128, 1), 256>>>(
            ctx, Wv, V, nullptr, CDIM, CDIM, INNER, INNER,
            1, 0,0, 0,0, 0,0);

    // 4) S[b,h] = Q[b,:,h,:] @ K[b,:,h,:]^T    [4096,64] x [1024,64]^T
    mma_gemm<128,128,16,32,64,true,false>
        <<<dim3(SEQ_M/128, SEQ_N/128, BATCH*HEADS), 256>>>(
            Q, Kb, S, nullptr, DHEAD, INNER, INNER, SEQ_M,
            HEADS,
            (size_t)SEQ_N * INNER, (size_t)DHEAD,
            (size_t)SEQ_M * INNER, (size_t)DHEAD,
            (size_t)HEADS * SNM,   SNM);

    // 5) softmax rows of S, scale = 1/sqrt(64)
    softmax_kernel<<<(unsigned)((size_t)BATCH * HEADS * SEQ_N), 256>>>(S, 0.125f);

    // 6) O[b,:,h,:] = P[b,h] @ V[b,:,h,:]      [4096,1024] x [1024,64]
    mma_gemm<128,64,16,32,32,false,false>
        <<<dim3(DHEAD/64, SEQ_N/128, BATCH*HEADS), 256>>>(
            S, V, O, nullptr, SEQ_M, SEQ_M, INNER, INNER,
            HEADS,
            (size_t)HEADS * SNM,   SNM,
            (size_t)SEQ_M * INNER, (size_t)DHEAD,
            (size_t)SEQ_N * INNER, (size_t)DHEAD);

    // 7) out = O @ Wo + bo   [16384,1024] x [1024,1024]
    mma_gemm<128,128,16,32,64,false,true>
        <<<dim3(INNER/128, ROWS_Q/128, 1), 256>>>(
            O, Wo, out, bo, INNER, INNER, QDIM, QDIM,
            1, 0,0, 0,0, 0,0);
}

// round 8
// speedup vs baseline: 1.4978x; 1.3383x over previous
#include <cuda_runtime.h>
#include <cstddef>
#include <cstdint>

// ---------------------------------------------------------------------------
// CrossAttention: out = softmax((xWq)(ctxWk)^T * D^-0.5) (ctxWv) Wo + bo
// B=4, N=4096, M=1024, QUERY_DIM=1024, CONTEXT_DIM=768, H=16, D=64, INNER=1024
// Tensor-core GEMMs: mma.sync tf32, 3xTF32 split, cp.async pipeline, 2 CTA/SM.
// ---------------------------------------------------------------------------

#define BATCH      4
#define SEQ_N      4096
#define SEQ_M      1024
#define QDIM       1024
#define CDIM       768
#define HEADS      16
#define DHEAD      64
#define INNER      1024
#define ROWS_Q     (BATCH * SEQ_N)   // 16384
#define ROWS_KV    (BATCH * SEQ_M)   // 4096

__device__ float g_Q[(size_t)ROWS_Q  * INNER];
__device__ float g_K[(size_t)ROWS_KV * INNER];
__device__ float g_V[(size_t)ROWS_KV * INNER];
__device__ float g_S[(size_t)BATCH * HEADS * SEQ_N * SEQ_M]; // 1 GB scores
__device__ float g_O[(size_t)ROWS_Q  * INNER];

// ---------------------------------------------------------------------------
// helpers
// ---------------------------------------------------------------------------
__device__ __forceinline__ void split_tf32(float x, uint32_t& h, uint32_t& l) {
    asm("cvt.rna.tf32.f32 %0, %1;" : "=r"(h) : "f"(x));
    float lo = x - __uint_as_float(h);
    asm("cvt.rna.tf32.f32 %0, %1;" : "=r"(l) : "f"(lo));
}

__device__ __forceinline__ void mma_tf32(float* c, const uint32_t* a, const uint32_t* b) {
    asm volatile(
        "mma.sync.aligned.m16n8k8.row.col.f32.tf32.tf32.f32 "
        "{%0,%1,%2,%3}, {%4,%5,%6,%7}, {%8,%9}, {%0,%1,%2,%3};"
        : "+f"(c[0]), "+f"(c[1]), "+f"(c[2]), "+f"(c[3])
        : "r"(a[0]), "r"(a[1]), "r"(a[2]), "r"(a[3]),
          "r"(b[0]), "r"(b[1]));
}

__device__ __forceinline__ void cp16(void* smem, const void* gmem) {
    uint32_t s = (uint32_t)__cvta_generic_to_shared(smem);
    asm volatile("cp.async.cg.shared.global [%0], [%1], 16;" :: "r"(s), "l"(gmem));
}
#define CP_COMMIT() asm volatile("cp.async.commit_group;")
template<int N>
__device__ __forceinline__ void cp_wait() {
    asm volatile("cp.async.wait_group %0;" :: "n"(N));
}

// ---------------------------------------------------------------------------
// Tensor-core GEMM (tf32 x3 split, fp32 accumulate), cp.async double buffer.
//   C[M,N] = A[M,K] * B[K,N]          (TRANSB = false)
//   C[M,N] = A[M,K] * B[N,K]^T        (TRANSB = true)
// Batched over blockIdx.z: zb = z/zdiv, zh = z%zdiv; ptr += zb*s1 + zh*s2.
// ---------------------------------------------------------------------------
template<int BM, int BN, int BK, int WM, int WN, bool TRANSB, bool BIAS>
__global__ __launch_bounds__(256, 2)
void mma_gemm(const float* __restrict__ A,
              const float* __restrict__ B,
              float* __restrict__ C,
              const float* __restrict__ bias,
              int K, int lda, int ldb, int ldc,
              int zdiv,
              size_t sA1, size_t sA2,
              size_t sB1, size_t sB2,
              size_t sC1, size_t sC2)
{
    constexpr int WARPS_M = BM / WM;
    constexpr int WARPS_N = BN / WN;
    constexpr int THREADS = WARPS_M * WARPS_N * 32;
    constexpr int MF = WM / 16;
    constexpr int NF = WN / 8;
    constexpr int NC = (NF >= 4) ? 4 : NF;
    constexpr int A_IT = (BM * BK / 4) / THREADS;
    constexpr int B_IT = (BK * BN / 4) / THREADS;
    // raw fp32 tiles; padded strides keep cp.async stores + frag LDS conflict-free
    constexpr int SAK = BK + 4;                    // A: [BM][BK+4], K contiguous
    constexpr int B_D0 = TRANSB ? BN : BK;
    constexpr int B_D1 = TRANSB ? BK + 4 : BN + 8;
    static_assert((BM * BK / 4) % THREADS == 0, "A tile");
    static_assert((BK * BN / 4) % THREADS == 0, "B tile");
    static_assert(BK % 8 == 0 && WM % 16 == 0 && WN % 8 == 0 && NF % NC == 0, "tiles");

    __shared__ float As[2][BM][SAK];
    __shared__ float Bs[2][B_D0][B_D1];

    const int z  = blockIdx.z;
    const int zb = z / zdiv;
    const int zh = z % zdiv;
    const float* Ab = A + zb * sA1 + zh * sA2;
    const float* Bb = B + zb * sB1 + zh * sB2;
    float*       Cb = C + zb * sC1 + zh * sC2;

    const int tid  = threadIdx.x;
    const int wid  = tid >> 5;
    const int lane = tid & 31;
    const int gid  = lane >> 2;
    const int tig  = lane & 3;
    const int wm   = wid % WARPS_M;
    const int wn   = wid / WARPS_M;
    const int row0 = blockIdx.y * BM;
    const int col0 = blockIdx.x * BN;

    auto copyA = [&](int k0, int buf) {
#pragma unroll
        for (int i = 0; i < A_IT; i++) {
            int v   = tid + i * THREADS;
            int r   = v / (BK / 4);
            int kk4 = v % (BK / 4);
            cp16(&As[buf][r][kk4 * 4],
                 &Ab[(size_t)(row0 + r) * lda + k0 + kk4 * 4]);
        }
    };
    auto copyB = [&](int k0, int buf) {
        if (!TRANSB) {
#pragma unroll
            for (int i = 0; i < B_IT; i++) {
                int v  = tid + i * THREADS;
                int kk = v / (BN / 4);
                int c4 = v % (BN / 4);
                cp16(&Bs[buf][kk][c4 * 4],
                     &Bb[(size_t)(k0 + kk) * ldb + col0 + c4 * 4]);
            }
        } else {
#pragma unroll
            for (int i = 0; i < B_IT; i++) {
                int v   = tid + i * THREADS;
                int j   = v / (BK / 4);
                int kk4 = v % (BK / 4);
                cp16(&Bs[buf][j][kk4 * 4],
                     &Bb[(size_t)(col0 + j) * ldb + k0 + kk4 * 4]);
            }
        }
    };

    float acc[MF][NF][4];
#pragma unroll
    for (int mi = 0; mi < MF; mi++)
#pragma unroll
        for (int ni = 0; ni < NF; ni++)
#pragma unroll
            for (int q = 0; q < 4; q++) acc[mi][ni][q] = 0.f;

    const int nT = K / BK;
    copyA(0, 0); copyB(0, 0); CP_COMMIT();

    for (int t = 0; t < nT; t++) {
        const int cur = t & 1;
        if (t + 1 < nT) {
            copyA((t + 1) * BK, cur ^ 1);
            copyB((t + 1) * BK, cur ^ 1);
            CP_COMMIT();
            cp_wait<1>();          // tile t complete
        } else {
            cp_wait<0>();
        }
        __syncthreads();

#pragma unroll
        for (int ks = 0; ks < BK / 8; ks++) {
            const int k0 = ks * 8;
            uint32_t ah[MF][4], al[MF][4];
#pragma unroll
            for (int mi = 0; mi < MF; mi++) {
                int m = wm * WM + mi * 16;
                split_tf32(As[cur][m + gid    ][k0 + tig    ], ah[mi][0], al[mi][0]);
                split_tf32(As[cur][m + gid + 8][k0 + tig    ], ah[mi][1], al[mi][1]);
                split_tf32(As[cur][m + gid    ][k0 + tig + 4], ah[mi][2], al[mi][2]);
                split_tf32(As[cur][m + gid + 8][k0 + tig + 4], ah[mi][3], al[mi][3]);
            }
#pragma unroll
            for (int nc = 0; nc < NF / NC; nc++) {
                uint32_t bh[NC][2], bl[NC][2];
#pragma unroll
                for (int nj = 0; nj < NC; nj++) {
                    int n = wn * WN + (nc * NC + nj) * 8 + gid;
                    float y0, y1;
                    if (TRANSB) { y0 = Bs[cur][n][k0 + tig];  y1 = Bs[cur][n][k0 + tig + 4]; }
                    else        { y0 = Bs[cur][k0 + tig][n];  y1 = Bs[cur][k0 + tig + 4][n]; }
                    split_tf32(y0, bh[nj][0], bl[nj][0]);
                    split_tf32(y1, bh[nj][1], bl[nj][1]);
                }
#pragma unroll
                for (int mi = 0; mi < MF; mi++)
#pragma unroll
                    for (int nj = 0; nj < NC; nj++) {
                        float* c = acc[mi][nc * NC + nj];
                        mma_tf32(c, ah[mi], bh[nj]);   // hi*hi
                        mma_tf32(c, ah[mi], bl[nj]);   // hi*lo
                        mma_tf32(c, al[mi], bh[nj]);   // lo*hi
                    }
            }
        }
        __syncthreads();
    }

    // ---- epilogue ----
#pragma unroll
    for (int mi = 0; mi < MF; mi++) {
        int r = row0 + wm * WM + mi * 16 + gid;
#pragma unroll
        for (int ni = 0; ni < NF; ni++) {
            int c = col0 + wn * WN + ni * 8 + tig * 2;
            float2 v01, v23;
            v01.x = acc[mi][ni][0]; v01.y = acc[mi][ni][1];
            v23.x = acc[mi][ni][2]; v23.y = acc[mi][ni][3];
            if (BIAS) {
                float b0 = bias[c], b1 = bias[c + 1];
                v01.x += b0; v01.y += b1;
                v23.x += b0; v23.y += b1;
            }
            *reinterpret_cast<float2*>(&Cb[(size_t)r * ldc + c])       = v01;
            *reinterpret_cast<float2*>(&Cb[(size_t)(r + 8) * ldc + c]) = v23;
        }
    }
}

// ---------------------------------------------------------------------------
// Row softmax over 1024 columns (in place), with pre-scale.
// ---------------------------------------------------------------------------
__global__ void softmax_kernel(float* __restrict__ S, float scale)
{
    constexpr int VPT = 4;
    size_t row = blockIdx.x;
    float* p = S + row * 1024;
    int t = threadIdx.x;

    float v[VPT];
    float mx = -3.4e38f;
#pragma unroll
    for (int i = 0; i < VPT; i++) {
        v[i] = p[t + i * 256] * scale;
        mx = fmaxf(mx, v[i]);
    }

    __shared__ float red[8];
#pragma unroll
    for (int o = 16; o > 0; o >>= 1)
        mx = fmaxf(mx, __shfl_xor_sync(0xffffffffu, mx, o));
    if ((t & 31) == 0) red[t >> 5] = mx;
    __syncthreads();
    mx = red[0];
#pragma unroll
    for (int i = 1; i < 8; i++) mx = fmaxf(mx, red[i]);

    float sum = 0.f;
#pragma unroll
    for (int i = 0; i < VPT; i++) {
        v[i] = __expf(v[i] - mx);
        sum += v[i];
    }
#pragma unroll
    for (int o = 16; o > 0; o >>= 1)
        sum += __shfl_xor_sync(0xffffffffu, sum, o);
    __syncthreads();
    if ((t & 31) == 0) red[t >> 5] = sum;
    __syncthreads();
    sum = 0.f;
#pragma unroll
    for (int i = 0; i < 8; i++) sum += red[i];

    float inv = 1.f / sum;
#pragma unroll
    for (int i = 0; i < VPT; i++) p[t + i * 256] = v[i] * inv;
}

// ---------------------------------------------------------------------------
extern "C" void kernel_launch(void* const* d_in, const int* in_sizes, int n_in,
                              void* d_out, int out_size)
{
    const float* x   = (const float*)d_in[0];
    const float* ctx = (const float*)d_in[1];
    const float* Wq  = (const float*)d_in[2];
    const float* Wk  = (const float*)d_in[3];
    const float* Wv  = (const float*)d_in[4];
    const float* Wo  = (const float*)d_in[5];
    const float* bo  = (const float*)d_in[6];
    float* out = (float*)d_out;

    float *Q, *Kb, *V, *S, *O;
    cudaGetSymbolAddress((void**)&Q,  g_Q);
    cudaGetSymbolAddress((void**)&Kb, g_K);
    cudaGetSymbolAddress((void**)&V,  g_V);
    cudaGetSymbolAddress((void**)&S,  g_S);
    cudaGetSymbolAddress((void**)&O,  g_O);

    const size_t SNM = (size_t)SEQ_N * SEQ_M;

    // 1) Q = x @ Wq          [16384,1024] x [1024,1024]
    mma_gemm<128,128,16,32,64,false,false>
        <<<dim3(INNER/128, ROWS_Q/128, 1), 256>>>(
            x, Wq, Q, nullptr, QDIM, QDIM, INNER, INNER,
            1, 0,0, 0,0, 0,0);

    // 2) K = ctx @ Wk        [4096,768] x [768,1024]
    mma_gemm<128,128,16,32,64,false,false>
        <<<dim3(INNER/128, ROWS_KV/128, 1), 256>>>(
            ctx, Wk, Kb, nullptr, CDIM, CDIM, INNER, INNER,
            1, 0,0, 0,0, 0,0);

    // 3) V = ctx @ Wv
    mma_gemm<128,128,16,32,64,false,false>
        <<<dim3(INNER/128, ROWS_KV/128, 1), 256>>>(
            ctx, Wv, V, nullptr, CDIM, CDIM, INNER, INNER,
            1, 0,0, 0,0, 0,0);

    // 4) S[b,h] = Q[b,:,h,:] @ K[b,:,h,:]^T    [4096,64] x [1024,64]^T
    mma_gemm<128,128,16,32,64,true,false>
        <<<dim3(SEQ_M/128, SEQ_N/128, BATCH*HEADS), 256>>>(
            Q, Kb, S, nullptr, DHEAD, INNER, INNER, SEQ_M,
            HEADS,
            (size_t)SEQ_N * INNER, (size_t)DHEAD,
            (size_t)SEQ_M * INNER, (size_t)DHEAD,
            (size_t)HEADS * SNM,   SNM);

    // 5) softmax rows of S, scale = 1/sqrt(64)
    softmax_kernel<<<(unsigned)((size_t)BATCH * HEADS * SEQ_N), 256>>>(S, 0.125f);

    // 6) O[b,:,h,:] = P[b,h] @ V[b,:,h,:]      [4096,1024] x [1024,64]
    mma_gemm<128,64,16,32,32,false,false>
        <<<dim3(DHEAD/64, SEQ_N/128, BATCH*HEADS), 256>>>(
            S, V, O, nullptr, SEQ_M, SEQ_M, INNER, INNER,
            HEADS,
            (size_t)HEADS * SNM,   SNM,
            (size_t)SEQ_M * INNER, (size_t)DHEAD,
            (size_t)SEQ_N * INNER, (size_t)DHEAD);

    // 7) out = O @ Wo + bo   [16384,1024] x [1024,1024]
    mma_gemm<128,128,16,32,64,false,true>
        <<<dim3(INNER/128, ROWS_Q/128, 1), 256>>>(
            O, Wo, out, bo, INNER, INNER, QDIM, QDIM,
            1, 0,0, 0,0, 0,0);
}

// round 9
// speedup vs baseline: 2.0040x; 1.3379x over previous
#include <cuda_runtime.h>
#include <cstddef>
#include <cstdint>

// ---------------------------------------------------------------------------
// CrossAttention via 3xBF16 tensor-core GEMMs (m16n8k16, fp32 accumulate).
// All operands pre-split into bf16 hi/lo pair-packed (u32 = 2 consecutive-K
// bf16) buffers; GEMM inner loop is pure LDS + HMMA.
// ---------------------------------------------------------------------------

#define BATCH 4
#define SEQ_N 4096
#define SEQ_M 1024
#define QDIM 1024
#define CDIM 768
#define HEADS 16
#define DHEAD 64
#define INNER 1024
#define ROWS_Q (BATCH * SEQ_N)   // 16384
#define ROWS_KV (BATCH * SEQ_M)  // 4096

// ---- scratch (static device globals) ----
__device__ uint32_t g_x_hi[(size_t)ROWS_Q * QDIM / 2],  g_x_lo[(size_t)ROWS_Q * QDIM / 2];
__device__ uint32_t g_c_hi[(size_t)ROWS_KV * CDIM / 2], g_c_lo[(size_t)ROWS_KV * CDIM / 2];
__device__ uint32_t g_Wq_hi[(size_t)INNER * QDIM / 2],  g_Wq_lo[(size_t)INNER * QDIM / 2];
__device__ uint32_t g_Wk_hi[(size_t)INNER * CDIM / 2],  g_Wk_lo[(size_t)INNER * CDIM / 2];
__device__ uint32_t g_Wv_hi[(size_t)INNER * CDIM / 2],  g_Wv_lo[(size_t)INNER * CDIM / 2];
__device__ uint32_t g_Wo_hi[(size_t)QDIM * INNER / 2],  g_Wo_lo[(size_t)QDIM * INNER / 2];
__device__ uint32_t g_Q_hi[(size_t)ROWS_Q * INNER / 2], g_Q_lo[(size_t)ROWS_Q * INNER / 2];
__device__ uint32_t g_K_hi[(size_t)ROWS_KV * INNER / 2], g_K_lo[(size_t)ROWS_KV * INNER / 2];
__device__ uint32_t g_V_hi[(size_t)ROWS_KV * INNER / 2], g_V_lo[(size_t)ROWS_KV * INNER / 2];
__device__ float    g_S[(size_t)BATCH * HEADS * SEQ_N * SEQ_M];                 // 1 GB
__device__ uint32_t g_P_hi[(size_t)BATCH * HEADS * SEQ_N * SEQ_M / 2];
__device__ uint32_t g_P_lo[(size_t)BATCH * HEADS * SEQ_N * SEQ_M / 2];
__device__ uint32_t g_O_hi[(size_t)ROWS_Q * INNER / 2], g_O_lo[(size_t)ROWS_Q * INNER / 2];

// ---------------------------------------------------------------------------
// helpers
// ---------------------------------------------------------------------------
__device__ __forceinline__ uint32_t pack2(float v0, float v1) {
    uint32_t r;
    asm("cvt.rn.bf16x2.f32 %0, %1, %2;" : "=r"(r) : "f"(v1), "f"(v0));  // low = v0
    return r;
}
__device__ __forceinline__ void split2(float v0, float v1, uint32_t& h, uint32_t& l) {
    h = pack2(v0, v1);
    float h0 = __uint_as_float(h << 16);
    float h1 = __uint_as_float(h & 0xffff0000u);
    l = pack2(v0 - h0, v1 - h1);
}
__device__ __forceinline__ void mma_bf16(float* c, const uint32_t* a, const uint32_t* b) {
    asm volatile(
        "mma.sync.aligned.m16n8k16.row.col.f32.bf16.bf16.f32 "
        "{%0,%1,%2,%3}, {%4,%5,%6,%7}, {%8,%9}, {%0,%1,%2,%3};"
        : "+f"(c[0]), "+f"(c[1]), "+f"(c[2]), "+f"(c[3])
        : "r"(a[0]), "r"(a[1]), "r"(a[2]), "r"(a[3]), "r"(b[0]), "r"(b[1]));
}
__device__ __forceinline__ void cp16(void* smem, const void* gmem) {
    uint32_t s = (uint32_t)__cvta_generic_to_shared(smem);
    asm volatile("cp.async.cg.shared.global [%0], [%1], 16;" :: "r"(s), "l"(gmem));
}
#define CP_COMMIT() asm volatile("cp.async.commit_group;")
template<int N> __device__ __forceinline__ void cp_wait() {
    asm volatile("cp.async.wait_group %0;" :: "n"(N));
}

// ---------------------------------------------------------------------------
// pre-split kernels
// ---------------------------------------------------------------------------
__global__ void split_pairs(const float2* __restrict__ src,
                            uint32_t* __restrict__ h, uint32_t* __restrict__ l, size_t n) {
    size_t i = (size_t)blockIdx.x * blockDim.x + threadIdx.x;
    if (i >= n) return;
    float2 v = src[i];
    uint32_t hh, ll;
    split2(v.x, v.y, hh, ll);
    h[i] = hh; l[i] = ll;
}

// W [K][N] f32 -> Th/Tl [N][K/2] bf16-pairs (transposed, K-major)
__global__ void split_transpose(const float* __restrict__ W,
                                uint32_t* __restrict__ Th, uint32_t* __restrict__ Tl,
                                int K, int N) {
    __shared__ float ts[32][33];
    int tx = threadIdx.x & 31, ty = threadIdx.x >> 5;
    int n0 = blockIdx.x * 32, k0 = blockIdx.y * 32;
#pragma unroll
    for (int i = 0; i < 4; i++)
        ts[ty + 8 * i][tx] = W[(size_t)(k0 + ty + 8 * i) * N + n0 + tx];
    __syncthreads();
#pragma unroll
    for (int rep = 0; rep < 2; rep++) {
        int idx = threadIdx.x + rep * 256;
        int nl = idx >> 4, kp = idx & 15;
        uint32_t hh, ll;
        split2(ts[2 * kp][nl], ts[2 * kp + 1][nl], hh, ll);
        size_t o = (size_t)(n0 + nl) * (K >> 1) + (k0 >> 1) + kp;
        Th[o] = hh; Tl[o] = ll;
    }
}

// ---------------------------------------------------------------------------
// Tensor-core GEMM, 3xBF16 emulation, cp.async double buffer.
//   C[M,N] = A[M,K] * B^T  (A: [M][K/2] pairs; B per BMODE)
// BMODE 0: B stored [N][K/2] u32 pairs (K-major)
// BMODE 1: B stored [K][ldb] bf16 elements (hi/lo planes), k-strided
// OMODE 0: f32   1: f32+bias   2: split hi/lo pair output
// ---------------------------------------------------------------------------
template<int BM, int BN, int WM, int WN, int BMODE, int OMODE>
__global__ __launch_bounds__(256, 2)
void mma_gemm(const uint32_t* __restrict__ Ah_, const uint32_t* __restrict__ Al_,
              const void* __restrict__ Bh_, const void* __restrict__ Bl_,
              void* __restrict__ C1, void* __restrict__ C2,
              const float* __restrict__ bias,
              int K, int lda, int ldb, int ldc, int zdiv,
              size_t sA1, size_t sA2, size_t sB1, size_t sB2,
              size_t sC1, size_t sC2)
{
    constexpr int BK = 16;
    constexpr int WARPS_M = BM / WM;
    constexpr int WARPS_N = BN / WN;
    constexpr int THREADS = WARPS_M * WARPS_N * 32;
    constexpr int MF = WM / 16;
    constexpr int NF = WN / 8;
    constexpr int NC = (NF >= 4) ? 4 : NF;
    constexpr int SA = 20;                 // u32 stride: [hi 0..7][lo 8..15][pad]
    constexpr int A_CH = BM * 4;           // 16B chunks per tile (hi2 + lo2 per row)
    constexpr int A_IT = A_CH / THREADS;
    static_assert(A_CH % THREADS == 0 && THREADS == 256, "cfg");
    static_assert(NF % NC == 0, "cfg");

    __shared__ uint32_t As[2][BM][SA];
    constexpr int BS_U32 = (BMODE == 0) ? 2 * BN * SA : (2 * 2 * BK * 72) / 2;
    __shared__ alignas(16) uint32_t BsRaw[BS_U32];
    auto BsP = (uint32_t(*)[BN][SA])BsRaw;        // BMODE 0 view
    auto BsN = (uint16_t(*)[2][BK][72])BsRaw;     // BMODE 1 view

    const int z = blockIdx.z, zb = z / zdiv, zh = z % zdiv;
    const uint32_t* Ah = Ah_ + zb * sA1 + zh * sA2;
    const uint32_t* Al = Al_ + zb * sA1 + zh * sA2;
    const uint32_t* Bph = nullptr; const uint32_t* Bpl = nullptr;
    const uint16_t* Bnh = nullptr; const uint16_t* Bnl = nullptr;
    if constexpr (BMODE == 0) {
        Bph = (const uint32_t*)Bh_ + zb * sB1 + zh * sB2;
        Bpl = (const uint32_t*)Bl_ + zb * sB1 + zh * sB2;
    } else {
        Bnh = (const uint16_t*)Bh_ + zb * sB1 + zh * sB2;
        Bnl = (const uint16_t*)Bl_ + zb * sB1 + zh * sB2;
    }

    const int tid = threadIdx.x;
    const int wid = tid >> 5, lane = tid & 31;
    const int gid = lane >> 2, tig = lane & 3;
    const int wm = wid % WARPS_M, wn = wid / WARPS_M;
    const int row0 = blockIdx.y * BM, col0 = blockIdx.x * BN;
    const int ldc2 = ldc >> 1;

    auto copyA = [&](int k0, int buf) {
#pragma unroll
        for (int i = 0; i < A_IT; i++) {
            int v = tid + i * THREADS;
            int r = v >> 2, q = v & 3;
            const uint32_t* src = (q < 2 ? Ah : Al)
                + (size_t)(row0 + r) * lda + (k0 >> 1) + (q & 1) * 4;
            cp16(&As[buf][r][(q & 1) * 4 + (q >> 1) * 8], src);
        }
    };
    auto copyB = [&](int k0, int buf) {
        if constexpr (BMODE == 0) {
            constexpr int B_CH = BN * 4;
            constexpr int B_IT = B_CH / THREADS;
#pragma unroll
            for (int i = 0; i < B_IT; i++) {
                int v = tid + i * THREADS;
                int r = v >> 2, q = v & 3;
                const uint32_t* src = (q < 2 ? Bph : Bpl)
                    + (size_t)(col0 + r) * ldb + (k0 >> 1) + (q & 1) * 4;
                cp16(&BsP[buf][r][(q & 1) * 4 + (q >> 1) * 8], src);
            }
        } else {
            constexpr int PL = BK * (BN / 8);       // chunks per plane
            constexpr int B_CH = 2 * PL;
            constexpr int B_IT = (B_CH + THREADS - 1) / THREADS;
#pragma unroll
            for (int i = 0; i < B_IT; i++) {
                int v = tid + i * THREADS;
                if (v < B_CH) {
                    int hl = v / PL, rem = v % PL;
                    int kk = rem / (BN / 8), c8 = rem % (BN / 8);
                    const uint16_t* src = (hl ? Bnl : Bnh)
                        + (size_t)(k0 + kk) * ldb + col0 + c8 * 8;
                    cp16(&BsN[buf][hl][kk][c8 * 8], src);
                }
            }
        }
    };

    float acc[MF][NF][4];
#pragma unroll
    for (int mi = 0; mi < MF; mi++)
#pragma unroll
        for (int ni = 0; ni < NF; ni++)
#pragma unroll
            for (int q = 0; q < 4; q++) acc[mi][ni][q] = 0.f;

    const int nT = K / BK;
    copyA(0, 0); copyB(0, 0); CP_COMMIT();

    for (int t = 0; t < nT; t++) {
        const int cur = t & 1;
        if (t + 1 < nT) {
            copyA((t + 1) * BK, cur ^ 1);
            copyB((t + 1) * BK, cur ^ 1);
            CP_COMMIT();
            cp_wait<1>();
        } else {
            cp_wait<0>();
        }
        __syncthreads();

        uint32_t ah[MF][4], al[MF][4];
#pragma unroll
        for (int mi = 0; mi < MF; mi++) {
            int m = wm * WM + mi * 16;
            ah[mi][0] = As[cur][m + gid    ][tig];
            ah[mi][1] = As[cur][m + gid + 8][tig];
            ah[mi][2] = As[cur][m + gid    ][tig + 4];
            ah[mi][3] = As[cur][m + gid + 8][tig + 4];
            al[mi][0] = As[cur][m + gid    ][tig + 8];
            al[mi][1] = As[cur][m + gid + 8][tig + 8];
            al[mi][2] = As[cur][m + gid    ][tig + 12];
            al[mi][3] = As[cur][m + gid + 8][tig + 12];
        }
#pragma unroll
        for (int nc = 0; nc < NF / NC; nc++) {
            uint32_t bh[NC][2], bl[NC][2];
#pragma unroll
            for (int nj = 0; nj < NC; nj++) {
                int n = wn * WN + (nc * NC + nj) * 8 + gid;
                if constexpr (BMODE == 0) {
                    bh[nj][0] = BsP[cur][n][tig];
                    bh[nj][1] = BsP[cur][n][tig + 4];
                    bl[nj][0] = BsP[cur][n][tig + 8];
                    bl[nj][1] = BsP[cur][n][tig + 12];
                } else {
                    bh[nj][0] = (uint32_t)BsN[cur][0][2 * tig    ][n]
                              | ((uint32_t)BsN[cur][0][2 * tig + 1][n] << 16);
                    bh[nj][1] = (uint32_t)BsN[cur][0][2 * tig + 8][n]
                              | ((uint32_t)BsN[cur][0][2 * tig + 9][n] << 16);
                    bl[nj][0] = (uint32_t)BsN[cur][1][2 * tig    ][n]
                              | ((uint32_t)BsN[cur][1][2 * tig + 1][n] << 16);
                    bl[nj][1] = (uint32_t)BsN[cur][1][2 * tig + 8][n]
                              | ((uint32_t)BsN[cur][1][2 * tig + 9][n] << 16);
                }
            }
#pragma unroll
            for (int mi = 0; mi < MF; mi++)
#pragma unroll
                for (int nj = 0; nj < NC; nj++) {
                    float* c = acc[mi][nc * NC + nj];
                    mma_bf16(c, ah[mi], bh[nj]);
                    mma_bf16(c, ah[mi], bl[nj]);
                    mma_bf16(c, al[mi], bh[nj]);
                }
        }
        __syncthreads();
    }

    // ---- epilogue ----
    if constexpr (OMODE < 2) {
        float* Cf = (float*)C1 + zb * sC1 + zh * sC2;
#pragma unroll
        for (int mi = 0; mi < MF; mi++) {
            int r = row0 + wm * WM + mi * 16 + gid;
#pragma unroll
            for (int ni = 0; ni < NF; ni++) {
                int c = col0 + wn * WN + ni * 8 + tig * 2;
                float2 v01, v23;
                v01.x = acc[mi][ni][0]; v01.y = acc[mi][ni][1];
                v23.x = acc[mi][ni][2]; v23.y = acc[mi][ni][3];
                if (OMODE == 1) {
                    float b0 = bias[c], b1 = bias[c + 1];
                    v01.x += b0; v01.y += b1;
                    v23.x += b0; v23.y += b1;
                }
                *reinterpret_cast<float2*>(&Cf[(size_t)r * ldc + c])       = v01;
                *reinterpret_cast<float2*>(&Cf[(size_t)(r + 8) * ldc + c]) = v23;
            }
        }
    } else {
        uint32_t* Chp = (uint32_t*)C1 + ((zb * sC1 + zh * sC2) >> 1);
        uint32_t* Clp = (uint32_t*)C2 + ((zb * sC1 + zh * sC2) >> 1);
#pragma unroll
        for (int mi = 0; mi < MF; mi++) {
            int r = row0 + wm * WM + mi * 16 + gid;
#pragma unroll
            for (int ni = 0; ni < NF; ni++) {
                int c = col0 + wn * WN + ni * 8 + tig * 2;
                uint32_t h0, l0, h1, l1;
                split2(acc[mi][ni][0], acc[mi][ni][1], h0, l0);
                split2(acc[mi][ni][2], acc[mi][ni][3], h1, l1);
                Chp[(size_t)r * ldc2 + (c >> 1)]       = h0;
                Clp[(size_t)r * ldc2 + (c >> 1)]       = l0;
                Chp[(size_t)(r + 8) * ldc2 + (c >> 1)] = h1;
                Clp[(size_t)(r + 8) * ldc2 + (c >> 1)] = l1;
            }
        }
    }
}

// ---------------------------------------------------------------------------
// Row softmax over 1024 cols: reads f32 S, writes split P (hi/lo pairs).
// 256 threads, 4 consecutive cols per thread.
// ---------------------------------------------------------------------------
__global__ void softmax_split(const float* __restrict__ S,
                              uint32_t* __restrict__ Ph, uint32_t* __restrict__ Pl,
                              float scale)
{
    size_t row = blockIdx.x;
    int t = threadIdx.x;
    float4 v = reinterpret_cast<const float4*>(S + row * 1024)[t];
    v.x *= scale; v.y *= scale; v.z *= scale; v.w *= scale;

    float mx = fmaxf(fmaxf(v.x, v.y), fmaxf(v.z, v.w));
    __shared__ float red[8];
#pragma unroll
    for (int o = 16; o > 0; o >>= 1)
        mx = fmaxf(mx, __shfl_xor_sync(0xffffffffu, mx, o));
    if ((t & 31) == 0) red[t >> 5] = mx;
    __syncthreads();
    mx = red[0];
#pragma unroll
    for (int i = 1; i < 8; i++) mx = fmaxf(mx, red[i]);

    v.x = __expf(v.x - mx); v.y = __expf(v.y - mx);
    v.z = __expf(v.z - mx); v.w = __expf(v.w - mx);
    float sum = v.x + v.y + v.z + v.w;
#pragma unroll
    for (int o = 16; o > 0; o >>= 1)
        sum += __shfl_xor_sync(0xffffffffu, sum, o);
    __syncthreads();
    if ((t & 31) == 0) red[t >> 5] = sum;
    __syncthreads();
    sum = 0.f;
#pragma unroll
    for (int i = 0; i < 8; i++) sum += red[i];

    float inv = 1.f / sum;
    v.x *= inv; v.y *= inv; v.z *= inv; v.w *= inv;

    uint32_t h0, l0, h1, l1;
    split2(v.x, v.y, h0, l0);
    split2(v.z, v.w, h1, l1);
    reinterpret_cast<uint2*>(Ph + row * 512)[t] = make_uint2(h0, h1);
    reinterpret_cast<uint2*>(Pl + row * 512)[t] = make_uint2(l0, l1);
}

// ---------------------------------------------------------------------------
extern "C" void kernel_launch(void* const* d_in, const int* in_sizes, int n_in,
                              void* d_out, int out_size)
{
    const float* x   = (const float*)d_in[0];
    const float* ctx = (const float*)d_in[1];
    const float* Wq  = (const float*)d_in[2];
    const float* Wk  = (const float*)d_in[3];
    const float* Wv  = (const float*)d_in[4];
    const float* Wo  = (const float*)d_in[5];
    const float* bo  = (const float*)d_in[6];
    float* out = (float*)d_out;

    uint32_t *Xh, *Xl, *Ch, *Cl, *Wqh, *Wql, *Wkh, *Wkl, *Wvh, *Wvl, *Woh, *Wol;
    uint32_t *Qh, *Ql, *Kh, *Kl, *Vh, *Vl, *Ph, *Pl, *Oh, *Ol;
    float* S;
    cudaGetSymbolAddress((void**)&Xh, g_x_hi);  cudaGetSymbolAddress((void**)&Xl, g_x_lo);
    cudaGetSymbolAddress((void**)&Ch, g_c_hi);  cudaGetSymbolAddress((void**)&Cl, g_c_lo);
    cudaGetSymbolAddress((void**)&Wqh, g_Wq_hi); cudaGetSymbolAddress((void**)&Wql, g_Wq_lo);
    cudaGetSymbolAddress((void**)&Wkh, g_Wk_hi); cudaGetSymbolAddress((void**)&Wkl, g_Wk_lo);
    cudaGetSymbolAddress((void**)&Wvh, g_Wv_hi); cudaGetSymbolAddress((void**)&Wvl, g_Wv_lo);
    cudaGetSymbolAddress((void**)&Woh, g_Wo_hi); cudaGetSymbolAddress((void**)&Wol, g_Wo_lo);
    cudaGetSymbolAddress((void**)&Qh, g_Q_hi);  cudaGetSymbolAddress((void**)&Ql, g_Q_lo);
    cudaGetSymbolAddress((void**)&Kh, g_K_hi);  cudaGetSymbolAddress((void**)&Kl, g_K_lo);
    cudaGetSymbolAddress((void**)&Vh, g_V_hi);  cudaGetSymbolAddress((void**)&Vl, g_V_lo);
    cudaGetSymbolAddress((void**)&Ph, g_P_hi);  cudaGetSymbolAddress((void**)&Pl, g_P_lo);
    cudaGetSymbolAddress((void**)&Oh, g_O_hi);  cudaGetSymbolAddress((void**)&Ol, g_O_lo);
    cudaGetSymbolAddress((void**)&S, g_S);

    const size_t SNM = (size_t)SEQ_N * SEQ_M;

    // ---- pre-split inputs ----
    split_pairs<<<(unsigned)((size_t)ROWS_Q * QDIM / 2 / 256), 256>>>(
        (const float2*)x, Xh, Xl, (size_t)ROWS_Q * QDIM / 2);
    split_pairs<<<(unsigned)((size_t)ROWS_KV * CDIM / 2 / 256), 256>>>(
        (const float2*)ctx, Ch, Cl, (size_t)ROWS_KV * CDIM / 2);
    split_transpose<<<dim3(INNER / 32, QDIM / 32), 256>>>(Wq, Wqh, Wql, QDIM, INNER);
    split_transpose<<<dim3(INNER / 32, CDIM / 32), 256>>>(Wk, Wkh, Wkl, CDIM, INNER);
    split_transpose<<<dim3(INNER / 32, CDIM / 32), 256>>>(Wv, Wvh, Wvl, CDIM, INNER);
    split_transpose<<<dim3(QDIM / 32, INNER / 32), 256>>>(Wo, Woh, Wol, INNER, QDIM);

    // 1) Q = x @ Wq -> split
    mma_gemm<128,128,32,64,0,2><<<dim3(INNER/128, ROWS_Q/128, 1), 256>>>(
        Xh, Xl, Wqh, Wql, Qh, Ql, nullptr,
        QDIM, QDIM/2, QDIM/2, INNER, 1, 0,0, 0,0, 0,0);

    // 2) K = ctx @ Wk -> split
    mma_gemm<128,128,32,64,0,2><<<dim3(INNER/128, ROWS_KV/128, 1), 256>>>(
        Ch, Cl, Wkh, Wkl, Kh, Kl, nullptr,
        CDIM, CDIM/2, CDIM/2, INNER, 1, 0,0, 0,0, 0,0);

    // 3) V = ctx @ Wv -> split
    mma_gemm<128,128,32,64,0,2><<<dim3(INNER/128, ROWS_KV/128, 1), 256>>>(
        Ch, Cl, Wvh, Wvl, Vh, Vl, nullptr,
        CDIM, CDIM/2, CDIM/2, INNER, 1, 0,0, 0,0, 0,0);

    // 4) S = Q @ K^T (per b,h) -> f32
    mma_gemm<128,128,32,64,0,0><<<dim3(SEQ_M/128, SEQ_N/128, BATCH*HEADS), 256>>>(
        Qh, Ql, Kh, Kl, S, nullptr, nullptr,
        DHEAD, INNER/2, INNER/2, SEQ_M, HEADS,
        (size_t)SEQ_N * (INNER/2), (size_t)(DHEAD/2),
        (size_t)SEQ_M * (INNER/2), (size_t)(DHEAD/2),
        (size_t)HEADS * SNM, SNM);

    // 5) softmax -> split P
    softmax_split<<<(unsigned)((size_t)BATCH * HEADS * SEQ_N), 256>>>(S, Ph, Pl, 0.125f);

    // 6) O = P @ V (per b,h) -> split (B in natural [k][n] bf16 layout)
    mma_gemm<128,64,32,32,1,2><<<dim3(DHEAD/64, SEQ_N/128, BATCH*HEADS), 256>>>(
        Ph, Pl, Vh, Vl, Oh, Ol, nullptr,
        SEQ_M, SEQ_M/2, INNER, INNER, HEADS,
        (size_t)HEADS * (SNM/2), SNM/2,
        (size_t)SEQ_M * INNER, (size_t)DHEAD,
        (size_t)SEQ_N * INNER, (size_t)DHEAD);

    // 7) out = O @ Wo + bo -> f32
    mma_gemm<128,128,32,64,0,1><<<dim3(QDIM/128, ROWS_Q/128, 1), 256>>>(
        Oh, Ol, Woh, Wol, out, nullptr, bo,
        INNER, INNER/2, INNER/2, QDIM, 1, 0,0, 0,0, 0,0);
}

// round 10
// speedup vs baseline: 2.8352x; 1.4148x over previous
#include <cuda_runtime.h>
#include <cstddef>
#include <cstdint>

// ---------------------------------------------------------------------------
// CrossAttention via 3xBF16 tensor-core GEMMs + fused flash attention.
// All operands pre-split into bf16 hi/lo pair-packed (u32 = 2 consecutive-K
// bf16) buffers; GEMM inner loops are pure LDS + HMMA.
// ---------------------------------------------------------------------------

#define BATCH 4
#define SEQ_N 4096
#define SEQ_M 1024
#define QDIM 1024
#define CDIM 768
#define HEADS 16
#define DHEAD 64
#define INNER 1024
#define ROWS_Q (BATCH * SEQ_N)   // 16384
#define ROWS_KV (BATCH * SEQ_M)  // 4096

// ---- scratch (static device globals) ----
__device__ uint32_t g_x_hi[(size_t)ROWS_Q * QDIM / 2],  g_x_lo[(size_t)ROWS_Q * QDIM / 2];
__device__ uint32_t g_c_hi[(size_t)ROWS_KV * CDIM / 2], g_c_lo[(size_t)ROWS_KV * CDIM / 2];
__device__ uint32_t g_Wq_hi[(size_t)INNER * QDIM / 2],  g_Wq_lo[(size_t)INNER * QDIM / 2];
__device__ uint32_t g_Wk_hi[(size_t)INNER * CDIM / 2],  g_Wk_lo[(size_t)INNER * CDIM / 2];
__device__ uint32_t g_Wv_hi[(size_t)INNER * CDIM / 2],  g_Wv_lo[(size_t)INNER * CDIM / 2];
__device__ uint32_t g_Wo_hi[(size_t)QDIM * INNER / 2],  g_Wo_lo[(size_t)QDIM * INNER / 2];
__device__ uint32_t g_Q_hi[(size_t)ROWS_Q * INNER / 2], g_Q_lo[(size_t)ROWS_Q * INNER / 2];
__device__ uint32_t g_K_hi[(size_t)ROWS_KV * INNER / 2], g_K_lo[(size_t)ROWS_KV * INNER / 2];
__device__ uint32_t g_V_hi[(size_t)ROWS_KV * INNER / 2], g_V_lo[(size_t)ROWS_KV * INNER / 2];
__device__ uint32_t g_O_hi[(size_t)ROWS_Q * INNER / 2], g_O_lo[(size_t)ROWS_Q * INNER / 2];

// ---------------------------------------------------------------------------
// helpers
// ---------------------------------------------------------------------------
__device__ __forceinline__ uint32_t pack2(float v0, float v1) {
    uint32_t r;
    asm("cvt.rn.bf16x2.f32 %0, %1, %2;" : "=r"(r) : "f"(v1), "f"(v0));  // low = v0
    return r;
}
__device__ __forceinline__ void split2(float v0, float v1, uint32_t& h, uint32_t& l) {
    h = pack2(v0, v1);
    float h0 = __uint_as_float(h << 16);
    float h1 = __uint_as_float(h & 0xffff0000u);
    l = pack2(v0 - h0, v1 - h1);
}
__device__ __forceinline__ void mma_bf16(float* c, const uint32_t* a, const uint32_t* b) {
    asm volatile(
        "mma.sync.aligned.m16n8k16.row.col.f32.bf16.bf16.f32 "
        "{%0,%1,%2,%3}, {%4,%5,%6,%7}, {%8,%9}, {%0,%1,%2,%3};"
        : "+f"(c[0]), "+f"(c[1]), "+f"(c[2]), "+f"(c[3])
        : "r"(a[0]), "r"(a[1]), "r"(a[2]), "r"(a[3]), "r"(b[0]), "r"(b[1]));
}
__device__ __forceinline__ void cp16(void* smem, const void* gmem) {
    uint32_t s = (uint32_t)__cvta_generic_to_shared(smem);
    asm volatile("cp.async.cg.shared.global [%0], [%1], 16;" :: "r"(s), "l"(gmem));
}
#define CP_COMMIT() asm volatile("cp.async.commit_group;")
template<int N> __device__ __forceinline__ void cp_wait() {
    asm volatile("cp.async.wait_group %0;" :: "n"(N));
}

// ---------------------------------------------------------------------------
// pre-split kernels
// ---------------------------------------------------------------------------
__global__ void split_pairs(const float2* __restrict__ src,
                            uint32_t* __restrict__ h, uint32_t* __restrict__ l, size_t n) {
    size_t i = (size_t)blockIdx.x * blockDim.x + threadIdx.x;
    if (i >= n) return;
    float2 v = src[i];
    uint32_t hh, ll;
    split2(v.x, v.y, hh, ll);
    h[i] = hh; l[i] = ll;
}

// W [K][N] f32 -> Th/Tl [N][K/2] bf16-pairs (transposed, K-major)
__global__ void split_transpose(const float* __restrict__ W,
                                uint32_t* __restrict__ Th, uint32_t* __restrict__ Tl,
                                int K, int N) {
    __shared__ float ts[32][33];
    int tx = threadIdx.x & 31, ty = threadIdx.x >> 5;
    int n0 = blockIdx.x * 32, k0 = blockIdx.y * 32;
#pragma unroll
    for (int i = 0; i < 4; i++)
        ts[ty + 8 * i][tx] = W[(size_t)(k0 + ty + 8 * i) * N + n0 + tx];
    __syncthreads();
#pragma unroll
    for (int rep = 0; rep < 2; rep++) {
        int idx = threadIdx.x + rep * 256;
        int nl = idx >> 4, kp = idx & 15;
        uint32_t hh, ll;
        split2(ts[2 * kp][nl], ts[2 * kp + 1][nl], hh, ll);
        size_t o = (size_t)(n0 + nl) * (K >> 1) + (k0 >> 1) + kp;
        Th[o] = hh; Tl[o] = ll;
    }
}

// ---------------------------------------------------------------------------
// Tensor-core GEMM, 3xBF16 emulation, cp.async double buffer.
//   C[M,N] = A[M,K] * B^T  (A: [M][K/2] pairs; B: [N][K/2] pairs)
// OMODE 0: f32   1: f32+bias   2: split hi/lo pair output
// ---------------------------------------------------------------------------
template<int BM, int BN, int WM, int WN, int OMODE>
__global__ __launch_bounds__(256, 2)
void mma_gemm(const uint32_t* __restrict__ Ah_, const uint32_t* __restrict__ Al_,
              const uint32_t* __restrict__ Bh_, const uint32_t* __restrict__ Bl_,
              void* __restrict__ C1, void* __restrict__ C2,
              const float* __restrict__ bias,
              int K, int lda, int ldb, int ldc, int zdiv,
              size_t sA1, size_t sA2, size_t sB1, size_t sB2,
              size_t sC1, size_t sC2)
{
    constexpr int BK = 16;
    constexpr int WARPS_M = BM / WM;
    constexpr int WARPS_N = BN / WN;
    constexpr int THREADS = WARPS_M * WARPS_N * 32;
    constexpr int MF = WM / 16;
    constexpr int NF = WN / 8;
    constexpr int NC = (NF >= 4) ? 4 : NF;
    constexpr int SA = 20;                 // u32 stride: [hi 0..7][lo 8..15][pad]
    constexpr int A_IT = (BM * 4) / THREADS;
    constexpr int B_IT = (BN * 4) / THREADS;
    static_assert((BM * 4) % THREADS == 0 && THREADS == 256, "cfg");
    static_assert(NF % NC == 0, "cfg");

    __shared__ uint32_t As[2][BM][SA];
    __shared__ uint32_t Bs[2][BN][SA];

    const int z = blockIdx.z, zb = z / zdiv, zh = z % zdiv;
    const uint32_t* Ah = Ah_ + zb * sA1 + zh * sA2;
    const uint32_t* Al = Al_ + zb * sA1 + zh * sA2;
    const uint32_t* Bh = Bh_ + zb * sB1 + zh * sB2;
    const uint32_t* Bl = Bl_ + zb * sB1 + zh * sB2;

    const int tid = threadIdx.x;
    const int wid = tid >> 5, lane = tid & 31;
    const int gid = lane >> 2, tig = lane & 3;
    const int wm = wid % WARPS_M, wn = wid / WARPS_M;
    const int row0 = blockIdx.y * BM, col0 = blockIdx.x * BN;
    const int ldc2 = ldc >> 1;

    auto copyA = [&](int k0, int buf) {
#pragma unroll
        for (int i = 0; i < A_IT; i++) {
            int v = tid + i * THREADS;
            int r = v >> 2, q = v & 3;
            const uint32_t* src = (q < 2 ? Ah : Al)
                + (size_t)(row0 + r) * lda + (k0 >> 1) + (q & 1) * 4;
            cp16(&As[buf][r][(q & 1) * 4 + (q >> 1) * 8], src);
        }
    };
    auto copyB = [&](int k0, int buf) {
#pragma unroll
        for (int i = 0; i < B_IT; i++) {
            int v = tid + i * THREADS;
            int r = v >> 2, q = v & 3;
            const uint32_t* src = (q < 2 ? Bh : Bl)
                + (size_t)(col0 + r) * ldb + (k0 >> 1) + (q & 1) * 4;
            cp16(&Bs[buf][r][(q & 1) * 4 + (q >> 1) * 8], src);
        }
    };

    float acc[MF][NF][4];
#pragma unroll
    for (int mi = 0; mi < MF; mi++)
#pragma unroll
        for (int ni = 0; ni < NF; ni++)
#pragma unroll
            for (int q = 0; q < 4; q++) acc[mi][ni][q] = 0.f;

    const int nT = K / BK;
    copyA(0, 0); copyB(0, 0); CP_COMMIT();

    for (int t = 0; t < nT; t++) {
        const int cur = t & 1;
        if (t + 1 < nT) {
            copyA((t + 1) * BK, cur ^ 1);
            copyB((t + 1) * BK, cur ^ 1);
            CP_COMMIT();
            cp_wait<1>();
        } else {
            cp_wait<0>();
        }
        __syncthreads();

        uint32_t ah[MF][4], al[MF][4];
#pragma unroll
        for (int mi = 0; mi < MF; mi++) {
            int m = wm * WM + mi * 16;
            ah[mi][0] = As[cur][m + gid    ][tig];
            ah[mi][1] = As[cur][m + gid + 8][tig];
            ah[mi][2] = As[cur][m + gid    ][tig + 4];
            ah[mi][3] = As[cur][m + gid + 8][tig + 4];
            al[mi][0] = As[cur][m + gid    ][tig + 8];
            al[mi][1] = As[cur][m + gid + 8][tig + 8];
            al[mi][2] = As[cur][m + gid    ][tig + 12];
            al[mi][3] = As[cur][m + gid + 8][tig + 12];
        }
#pragma unroll
        for (int nc = 0; nc < NF / NC; nc++) {
            uint32_t bh[NC][2], bl[NC][2];
#pragma unroll
            for (int nj = 0; nj < NC; nj++) {
                int n = wn * WN + (nc * NC + nj) * 8 + gid;
                bh[nj][0] = Bs[cur][n][tig];
                bh[nj][1] = Bs[cur][n][tig + 4];
                bl[nj][0] = Bs[cur][n][tig + 8];
                bl[nj][1] = Bs[cur][n][tig + 12];
            }
#pragma unroll
            for (int mi = 0; mi < MF; mi++)
#pragma unroll
                for (int nj = 0; nj < NC; nj++) {
                    float* c = acc[mi][nc * NC + nj];
                    mma_bf16(c, ah[mi], bh[nj]);
                    mma_bf16(c, ah[mi], bl[nj]);
                    mma_bf16(c, al[mi], bh[nj]);
                }
        }
        __syncthreads();
    }

    // ---- epilogue ----
    if constexpr (OMODE < 2) {
        float* Cf = (float*)C1 + zb * sC1 + zh * sC2;
#pragma unroll
        for (int mi = 0; mi < MF; mi++) {
            int r = row0 + wm * WM + mi * 16 + gid;
#pragma unroll
            for (int ni = 0; ni < NF; ni++) {
                int c = col0 + wn * WN + ni * 8 + tig * 2;
                float2 v01, v23;
                v01.x = acc[mi][ni][0]; v01.y = acc[mi][ni][1];
                v23.x = acc[mi][ni][2]; v23.y = acc[mi][ni][3];
                if (OMODE == 1) {
                    float b0 = bias[c], b1 = bias[c + 1];
                    v01.x += b0; v01.y += b1;
                    v23.x += b0; v23.y += b1;
                }
                *reinterpret_cast<float2*>(&Cf[(size_t)r * ldc + c])       = v01;
                *reinterpret_cast<float2*>(&Cf[(size_t)(r + 8) * ldc + c]) = v23;
            }
        }
    } else {
        uint32_t* Chp = (uint32_t*)C1 + ((zb * sC1 + zh * sC2) >> 1);
        uint32_t* Clp = (uint32_t*)C2 + ((zb * sC1 + zh * sC2) >> 1);
#pragma unroll
        for (int mi = 0; mi < MF; mi++) {
            int r = row0 + wm * WM + mi * 16 + gid;
#pragma unroll
            for (int ni = 0; ni < NF; ni++) {
                int c = col0 + wn * WN + ni * 8 + tig * 2;
                uint32_t h0, l0, h1, l1;
                split2(acc[mi][ni][0], acc[mi][ni][1], h0, l0);
                split2(acc[mi][ni][2], acc[mi][ni][3], h1, l1);
                Chp[(size_t)r * ldc2 + (c >> 1)]       = h0;
                Clp[(size_t)r * ldc2 + (c >> 1)]       = l0;
                Chp[(size_t)(r + 8) * ldc2 + (c >> 1)] = h1;
                Clp[(size_t)(r + 8) * ldc2 + (c >> 1)] = l1;
            }
        }
    }
}

// ---------------------------------------------------------------------------
// Fused flash attention: S = Q K^T * 0.125, online softmax, O = P V.
// Grid: (SEQ_N/128, BATCH*HEADS). 8 warps; warp w owns q-rows w*16..w*16+15
// and all 128 kv cols of each tile. 3xBF16 everywhere; P split in-register.
// Dynamic smem: double-buffered K (pairs) + V (bf16 element planes).
// ---------------------------------------------------------------------------
#define KROW 68
#define KT   (128 * KROW)        // u32 per K tile (hi+lo pairs)
#define VT   9216                // u32 per V tile (2 planes * 128 * 72 u16)
#define FBUF (KT + VT)           // 17920 u32 per buffer
#define FLASH_SMEM (2 * FBUF * 4)  // 143360 bytes

__global__ __launch_bounds__(256, 1)
void flash_attn(const uint32_t* __restrict__ Qh, const uint32_t* __restrict__ Ql,
                const uint32_t* __restrict__ Kh, const uint32_t* __restrict__ Kl,
                const uint16_t* __restrict__ Vh, const uint16_t* __restrict__ Vl,
                uint32_t* __restrict__ Oh, uint32_t* __restrict__ Ol)
{
    extern __shared__ uint32_t sm[];

    const int tid = threadIdx.x;
    const int wid = tid >> 5, lane = tid & 31;
    const int gid = lane >> 2, tig = lane & 3;
    const int bh = blockIdx.y, b = bh >> 4, h = bh & 15;
    const int n0 = blockIdx.x * 128;

    const size_t qrow0 = (size_t)b * SEQ_N + n0;
    const size_t krow0 = (size_t)b * SEQ_M;
    const int hp = h * 32;   // pair col offset (DHEAD/2)
    const int he = h * 64;   // element col offset

    auto copyTile = [&](int tt, int buf) {
        uint32_t* smK = sm + buf * FBUF;
        uint16_t* smV = (uint16_t*)(sm + buf * FBUF + KT);
        int m0 = tt * 128;
#pragma unroll
        for (int i = 0; i < 8; i++) {
            int v = tid + i * 256;
            int r = v >> 4, q = v & 15;
            const uint32_t* src = (q < 8 ? Kh : Kl)
                + (krow0 + m0 + r) * 512 + hp + (q & 7) * 4;
            cp16(&smK[r * KROW + (q >= 8 ? 32 : 0) + (q & 7) * 4], src);
        }
#pragma unroll
        for (int i = 0; i < 8; i++) {
            int v = tid + i * 256;
            int r = v >> 4, q = v & 15;
            const uint16_t* src = (q < 8 ? Vh : Vl)
                + (krow0 + m0 + r) * 1024 + he + (q & 7) * 8;
            cp16(&smV[(q >= 8 ? 128 * 72 : 0) + r * 72 + (q & 7) * 8], src);
        }
    };

    // Q fragments (held in registers for the whole CTA)
    uint32_t qh[4][4], ql[4][4];
    {
        size_t r0 = (qrow0 + wid * 16 + gid) * 512 + hp;
        size_t r8 = r0 + 8 * 512;
#pragma unroll
        for (int c = 0; c < 4; c++) {
            qh[c][0] = Qh[r0 + c * 8 + tig];
            qh[c][1] = Qh[r8 + c * 8 + tig];
            qh[c][2] = Qh[r0 + c * 8 + tig + 4];
            qh[c][3] = Qh[r8 + c * 8 + tig + 4];
            ql[c][0] = Ql[r0 + c * 8 + tig];
            ql[c][1] = Ql[r8 + c * 8 + tig];
            ql[c][2] = Ql[r0 + c * 8 + tig + 4];
            ql[c][3] = Ql[r8 + c * 8 + tig + 4];
        }
    }

    float o[8][4];
#pragma unroll
    for (int nj = 0; nj < 8; nj++)
#pragma unroll
        for (int q = 0; q < 4; q++) o[nj][q] = 0.f;
    float m0r = -1e30f, m1r = -1e30f;
    float l0r = 0.f, l1r = 0.f;

    copyTile(0, 0); CP_COMMIT();

    for (int tt = 0; tt < 8; tt++) {
        const int cur = tt & 1;
        if (tt < 7) { copyTile(tt + 1, cur ^ 1); CP_COMMIT(); cp_wait<1>(); }
        else        { cp_wait<0>(); }
        __syncthreads();

        const uint32_t* smK = sm + cur * FBUF;
        const uint16_t* smV = (const uint16_t*)(sm + cur * FBUF + KT);

        // ---- S = Q K^T ----
        float s[16][4];
#pragma unroll
        for (int nj = 0; nj < 16; nj++)
#pragma unroll
            for (int q = 0; q < 4; q++) s[nj][q] = 0.f;
#pragma unroll
        for (int nj = 0; nj < 16; nj++) {
            const uint32_t* kr = smK + (nj * 8 + gid) * KROW;
#pragma unroll
            for (int c = 0; c < 4; c++) {
                uint32_t kh2[2] = { kr[c * 8 + tig],      kr[c * 8 + tig + 4] };
                uint32_t kl2[2] = { kr[32 + c * 8 + tig], kr[32 + c * 8 + tig + 4] };
                mma_bf16(s[nj], qh[c], kh2);
                mma_bf16(s[nj], qh[c], kl2);
                mma_bf16(s[nj], ql[c], kh2);
            }
        }

        // ---- online softmax (rows gid and gid+8; quad = lanes sharing gid) ----
        float mt0 = -1e30f, mt1 = -1e30f;
#pragma unroll
        for (int nj = 0; nj < 16; nj++) {
            mt0 = fmaxf(mt0, fmaxf(s[nj][0], s[nj][1]));
            mt1 = fmaxf(mt1, fmaxf(s[nj][2], s[nj][3]));
        }
        mt0 = fmaxf(mt0, __shfl_xor_sync(0xffffffffu, mt0, 1));
        mt0 = fmaxf(mt0, __shfl_xor_sync(0xffffffffu, mt0, 2));
        mt1 = fmaxf(mt1, __shfl_xor_sync(0xffffffffu, mt1, 1));
        mt1 = fmaxf(mt1, __shfl_xor_sync(0xffffffffu, mt1, 2));
        float mn0 = fmaxf(m0r, mt0), mn1 = fmaxf(m1r, mt1);
        float a0 = __expf(0.125f * (m0r - mn0));
        float a1 = __expf(0.125f * (m1r - mn1));
        m0r = mn0; m1r = mn1;
        float ms0 = 0.125f * mn0, ms1 = 0.125f * mn1;
        float sum0 = 0.f, sum1 = 0.f;
#pragma unroll
        for (int nj = 0; nj < 16; nj++) {
            s[nj][0] = __expf(fmaf(s[nj][0], 0.125f, -ms0));
            s[nj][1] = __expf(fmaf(s[nj][1], 0.125f, -ms0));
            s[nj][2] = __expf(fmaf(s[nj][2], 0.125f, -ms1));
            s[nj][3] = __expf(fmaf(s[nj][3], 0.125f, -ms1));
            sum0 += s[nj][0] + s[nj][1];
            sum1 += s[nj][2] + s[nj][3];
        }
        sum0 += __shfl_xor_sync(0xffffffffu, sum0, 1);
        sum0 += __shfl_xor_sync(0xffffffffu, sum0, 2);
        sum1 += __shfl_xor_sync(0xffffffffu, sum1, 1);
        sum1 += __shfl_xor_sync(0xffffffffu, sum1, 2);
        l0r = l0r * a0 + sum0;
        l1r = l1r * a1 + sum1;
#pragma unroll
        for (int nj = 0; nj < 8; nj++) {
            o[nj][0] *= a0; o[nj][1] *= a0;
            o[nj][2] *= a1; o[nj][3] *= a1;
        }

        // ---- O += P V (P repacked in registers; acc layout == A-frag layout) ----
#pragma unroll
        for (int kc = 0; kc < 8; kc++) {
            uint32_t ph[4], pl[4];
            split2(s[2 * kc][0],     s[2 * kc][1],     ph[0], pl[0]);
            split2(s[2 * kc][2],     s[2 * kc][3],     ph[1], pl[1]);
            split2(s[2 * kc + 1][0], s[2 * kc + 1][1], ph[2], pl[2]);
            split2(s[2 * kc + 1][2], s[2 * kc + 1][3], ph[3], pl[3]);
            const uint16_t* vbh = smV + (16 * kc + 2 * tig) * 72;
            const uint16_t* vbl = vbh + 128 * 72;
#pragma unroll
            for (int nj = 0; nj < 8; nj++) {
                int n = nj * 8 + gid;
                uint32_t vh2[2], vl2[2];
                vh2[0] = (uint32_t)vbh[n]          | ((uint32_t)vbh[72 + n] << 16);
                vh2[1] = (uint32_t)vbh[8 * 72 + n] | ((uint32_t)vbh[9 * 72 + n] << 16);
                vl2[0] = (uint32_t)vbl[n]          | ((uint32_t)vbl[72 + n] << 16);
                vl2[1] = (uint32_t)vbl[8 * 72 + n] | ((uint32_t)vbl[9 * 72 + n] << 16);
                mma_bf16(o[nj], ph, vh2);
                mma_bf16(o[nj], ph, vl2);
                mma_bf16(o[nj], pl, vh2);
            }
        }
        __syncthreads();
    }

    // ---- epilogue: O /= l, write split pairs ----
    float i0 = 1.f / l0r, i1 = 1.f / l1r;
    size_t r0 = (qrow0 + wid * 16 + gid) * 512 + hp;
    size_t r8 = r0 + 8 * 512;
#pragma unroll
    for (int nj = 0; nj < 8; nj++) {
        uint32_t hh, ll;
        split2(o[nj][0] * i0, o[nj][1] * i0, hh, ll);
        Oh[r0 + nj * 4 + tig] = hh;  Ol[r0 + nj * 4 + tig] = ll;
        split2(o[nj][2] * i1, o[nj][3] * i1, hh, ll);
        Oh[r8 + nj * 4 + tig] = hh;  Ol[r8 + nj * 4 + tig] = ll;
    }
}

// ---------------------------------------------------------------------------
extern "C" void kernel_launch(void* const* d_in, const int* in_sizes, int n_in,
                              void* d_out, int out_size)
{
    const float* x   = (const float*)d_in[0];
    const float* ctx = (const float*)d_in[1];
    const float* Wq  = (const float*)d_in[2];
    const float* Wk  = (const float*)d_in[3];
    const float* Wv  = (const float*)d_in[4];
    const float* Wo  = (const float*)d_in[5];
    const float* bo  = (const float*)d_in[6];
    float* out = (float*)d_out;

    uint32_t *Xh, *Xl, *Ch, *Cl, *Wqh, *Wql, *Wkh, *Wkl, *Wvh, *Wvl, *Woh, *Wol;
    uint32_t *Qh, *Ql, *Kh, *Kl, *Vh, *Vl, *Oh, *Ol;
    cudaGetSymbolAddress((void**)&Xh, g_x_hi);  cudaGetSymbolAddress((void**)&Xl, g_x_lo);
    cudaGetSymbolAddress((void**)&Ch, g_c_hi);  cudaGetSymbolAddress((void**)&Cl, g_c_lo);
    cudaGetSymbolAddress((void**)&Wqh, g_Wq_hi); cudaGetSymbolAddress((void**)&Wql, g_Wq_lo);
    cudaGetSymbolAddress((void**)&Wkh, g_Wk_hi); cudaGetSymbolAddress((void**)&Wkl, g_Wk_lo);
    cudaGetSymbolAddress((void**)&Wvh, g_Wv_hi); cudaGetSymbolAddress((void**)&Wvl, g_Wv_lo);
    cudaGetSymbolAddress((void**)&Woh, g_Wo_hi); cudaGetSymbolAddress((void**)&Wol, g_Wo_lo);
    cudaGetSymbolAddress((void**)&Qh, g_Q_hi);  cudaGetSymbolAddress((void**)&Ql, g_Q_lo);
    cudaGetSymbolAddress((void**)&Kh, g_K_hi);  cudaGetSymbolAddress((void**)&Kl, g_K_lo);
    cudaGetSymbolAddress((void**)&Vh, g_V_hi);  cudaGetSymbolAddress((void**)&Vl, g_V_lo);
    cudaGetSymbolAddress((void**)&Oh, g_O_hi);  cudaGetSymbolAddress((void**)&Ol, g_O_lo);

    cudaFuncSetAttribute(flash_attn, cudaFuncAttributeMaxDynamicSharedMemorySize,
                         FLASH_SMEM);

    // ---- pre-split inputs ----
    split_pairs<<<(unsigned)((size_t)ROWS_Q * QDIM / 2 / 256), 256>>>(
        (const float2*)x, Xh, Xl, (size_t)ROWS_Q * QDIM / 2);
    split_pairs<<<(unsigned)((size_t)ROWS_KV * CDIM / 2 / 256), 256>>>(
        (const float2*)ctx, Ch, Cl, (size_t)ROWS_KV * CDIM / 2);
    split_transpose<<<dim3(INNER / 32, QDIM / 32), 256>>>(Wq, Wqh, Wql, QDIM, INNER);
    split_transpose<<<dim3(INNER / 32, CDIM / 32), 256>>>(Wk, Wkh, Wkl, CDIM, INNER);
    split_transpose<<<dim3(INNER / 32, CDIM / 32), 256>>>(Wv, Wvh, Wvl, CDIM, INNER);
    split_transpose<<<dim3(QDIM / 32, INNER / 32), 256>>>(Wo, Woh, Wol, INNER, QDIM);

    // 1) Q = x @ Wq -> split
    mma_gemm<128,128,32,64,2><<<dim3(INNER/128, ROWS_Q/128, 1), 256>>>(
        Xh, Xl, Wqh, Wql, Qh, Ql, nullptr,
        QDIM, QDIM/2, QDIM/2, INNER, 1, 0,0, 0,0, 0,0);

    // 2) K = ctx @ Wk -> split
    mma_gemm<128,128,32,64,2><<<dim3(INNER/128, ROWS_KV/128, 1), 256>>>(
        Ch, Cl, Wkh, Wkl, Kh, Kl, nullptr,
        CDIM, CDIM/2, CDIM/2, INNER, 1, 0,0, 0,0, 0,0);

    // 3) V = ctx @ Wv -> split
    mma_gemm<128,128,32,64,2><<<dim3(INNER/128, ROWS_KV/128, 1), 256>>>(
        Ch, Cl, Wvh, Wvl, Vh, Vl, nullptr,
        CDIM, CDIM/2, CDIM/2, INNER, 1, 0,0, 0,0, 0,0);

    // 4-6) fused flash attention -> split O
    flash_attn<<<dim3(SEQ_N/128, BATCH*HEADS), 256, FLASH_SMEM>>>(
        Qh, Ql, Kh, Kl, (const uint16_t*)Vh, (const uint16_t*)Vl, Oh, Ol);

    // 7) out = O @ Wo + bo -> f32
    mma_gemm<128,128,32,64,1><<<dim3(QDIM/128, ROWS_Q/128, 1), 256>>>(
        Oh, Ol, Woh, Wol, out, nullptr, bo,
        INNER, INNER/2, INNER/2, QDIM, 1, 0,0, 0,0, 0,0);
}

// round 11
// speedup vs baseline: 2.9430x; 1.0380x over previous
#include <cuda_runtime.h>
#include <cstddef>
#include <cstdint>

// ---------------------------------------------------------------------------
// CrossAttention via 3xBF16 tensor-core GEMMs + fused flash attention.
// All operands pre-split into bf16 hi/lo pair-packed (u32 = 2 consecutive-K
// bf16) buffers; GEMM inner loops are pure LDS + HMMA. 3-stage cp.async.
// V pre-transposed so flash PV fragments load as clean u32 pairs.
// ---------------------------------------------------------------------------

#define BATCH 4
#define SEQ_N 4096
#define SEQ_M 1024
#define QDIM 1024
#define CDIM 768
#define HEADS 16
#define DHEAD 64
#define INNER 1024
#define ROWS_Q (BATCH * SEQ_N)   // 16384
#define ROWS_KV (BATCH * SEQ_M)  // 4096

// ---- scratch (static device globals) ----
__device__ uint32_t g_x_hi[(size_t)ROWS_Q * QDIM / 2],  g_x_lo[(size_t)ROWS_Q * QDIM / 2];
__device__ uint32_t g_c_hi[(size_t)ROWS_KV * CDIM / 2], g_c_lo[(size_t)ROWS_KV * CDIM / 2];
__device__ uint32_t g_Wq_hi[(size_t)INNER * QDIM / 2],  g_Wq_lo[(size_t)INNER * QDIM / 2];
__device__ uint32_t g_Wk_hi[(size_t)INNER * CDIM / 2],  g_Wk_lo[(size_t)INNER * CDIM / 2];
__device__ uint32_t g_Wv_hi[(size_t)INNER * CDIM / 2],  g_Wv_lo[(size_t)INNER * CDIM / 2];
__device__ uint32_t g_Wo_hi[(size_t)QDIM * INNER / 2],  g_Wo_lo[(size_t)QDIM * INNER / 2];
__device__ uint32_t g_Q_hi[(size_t)ROWS_Q * INNER / 2], g_Q_lo[(size_t)ROWS_Q * INNER / 2];
__device__ uint32_t g_K_hi[(size_t)ROWS_KV * INNER / 2], g_K_lo[(size_t)ROWS_KV * INNER / 2];
__device__ float    g_Vf[(size_t)ROWS_KV * INNER];                       // f32 V
__device__ uint32_t g_VT_hi[(size_t)ROWS_KV * INNER / 2];                // V^T pairs
__device__ uint32_t g_VT_lo[(size_t)ROWS_KV * INNER / 2];
__device__ uint32_t g_O_hi[(size_t)ROWS_Q * INNER / 2], g_O_lo[(size_t)ROWS_Q * INNER / 2];

// ---------------------------------------------------------------------------
// helpers
// ---------------------------------------------------------------------------
__device__ __forceinline__ uint32_t pack2(float v0, float v1) {
    uint32_t r;
    asm("cvt.rn.bf16x2.f32 %0, %1, %2;" : "=r"(r) : "f"(v1), "f"(v0));  // low = v0
    return r;
}
__device__ __forceinline__ void split2(float v0, float v1, uint32_t& h, uint32_t& l) {
    h = pack2(v0, v1);
    float h0 = __uint_as_float(h << 16);
    float h1 = __uint_as_float(h & 0xffff0000u);
    l = pack2(v0 - h0, v1 - h1);
}
__device__ __forceinline__ void mma_bf16(float* c, const uint32_t* a, const uint32_t* b) {
    asm volatile(
        "mma.sync.aligned.m16n8k16.row.col.f32.bf16.bf16.f32 "
        "{%0,%1,%2,%3}, {%4,%5,%6,%7}, {%8,%9}, {%0,%1,%2,%3};"
        : "+f"(c[0]), "+f"(c[1]), "+f"(c[2]), "+f"(c[3])
        : "r"(a[0]), "r"(a[1]), "r"(a[2]), "r"(a[3]), "r"(b[0]), "r"(b[1]));
}
__device__ __forceinline__ void cp16(void* smem, const void* gmem) {
    uint32_t s = (uint32_t)__cvta_generic_to_shared(smem);
    asm volatile("cp.async.cg.shared.global [%0], [%1], 16;" :: "r"(s), "l"(gmem));
}
#define CP_COMMIT() asm volatile("cp.async.commit_group;")
template<int N> __device__ __forceinline__ void cp_wait() {
    asm volatile("cp.async.wait_group %0;" :: "n"(N));
}

// ---------------------------------------------------------------------------
// pre-split kernels
// ---------------------------------------------------------------------------
__global__ void split_pairs(const float2* __restrict__ src,
                            uint32_t* __restrict__ h, uint32_t* __restrict__ l, size_t n) {
    size_t i = (size_t)blockIdx.x * blockDim.x + threadIdx.x;
    if (i >= n) return;
    float2 v = src[i];
    uint32_t hh, ll;
    split2(v.x, v.y, hh, ll);
    h[i] = hh; l[i] = ll;
}

// W [K][N] f32 -> Th/Tl [N][K/2] bf16-pairs (transposed, K-major).
// Batched over blockIdx.z with per-z offsets z*K*N (in) / z*N*(K/2) (out).
__global__ void split_transpose(const float* __restrict__ W,
                                uint32_t* __restrict__ Th, uint32_t* __restrict__ Tl,
                                int K, int N) {
    __shared__ float ts[32][33];
    const size_t zi = (size_t)blockIdx.z * K * N;
    const size_t zo = (size_t)blockIdx.z * N * (K >> 1);
    int tx = threadIdx.x & 31, ty = threadIdx.x >> 5;
    int n0 = blockIdx.x * 32, k0 = blockIdx.y * 32;
#pragma unroll
    for (int i = 0; i < 4; i++)
        ts[ty + 8 * i][tx] = W[zi + (size_t)(k0 + ty + 8 * i) * N + n0 + tx];
    __syncthreads();
#pragma unroll
    for (int rep = 0; rep < 2; rep++) {
        int idx = threadIdx.x + rep * 256;
        int nl = idx >> 4, kp = idx & 15;
        uint32_t hh, ll;
        split2(ts[2 * kp][nl], ts[2 * kp + 1][nl], hh, ll);
        size_t o = zo + (size_t)(n0 + nl) * (K >> 1) + (k0 >> 1) + kp;
        Th[o] = hh; Tl[o] = ll;
    }
}

// ---------------------------------------------------------------------------
// Tensor-core GEMM, 3xBF16 emulation, 3-stage cp.async pipeline (dyn smem).
//   C[M,N] = A[M,K] * B^T  (A: [M][K/2] pairs; B: [N][K/2] pairs)
// OMODE 0: f32   1: f32+bias   2: split hi/lo pair output
// ---------------------------------------------------------------------------
#define GEMM_BM 128
#define GEMM_BN 128
#define GEMM_SA 20
#define GEMM_SMEM (3 * (GEMM_BM + GEMM_BN) * GEMM_SA * 4)   // 61440 bytes

template<int WM, int WN, int OMODE>
__global__ __launch_bounds__(256, 2)
void mma_gemm(const uint32_t* __restrict__ Ah_, const uint32_t* __restrict__ Al_,
              const uint32_t* __restrict__ Bh_, const uint32_t* __restrict__ Bl_,
              void* __restrict__ C1, void* __restrict__ C2,
              const float* __restrict__ bias,
              int K, int lda, int ldb, int ldc, int zdiv,
              size_t sA1, size_t sA2, size_t sB1, size_t sB2,
              size_t sC1, size_t sC2)
{
    constexpr int BM = GEMM_BM, BN = GEMM_BN, BK = 16;
    constexpr int WARPS_M = BM / WM;
    constexpr int WARPS_N = BN / WN;
    constexpr int THREADS = WARPS_M * WARPS_N * 32;
    constexpr int MF = WM / 16;
    constexpr int NF = WN / 8;
    constexpr int NC = (NF >= 4) ? 4 : NF;
    constexpr int SA = GEMM_SA;            // u32 stride: [hi 0..7][lo 8..15][pad]
    constexpr int A_IT = (BM * 4) / THREADS;
    constexpr int B_IT = (BN * 4) / THREADS;
    static_assert((BM * 4) % THREADS == 0 && THREADS == 256, "cfg");
    static_assert(NF % NC == 0, "cfg");

    extern __shared__ uint32_t smg[];
    auto As = (uint32_t(*)[BM][SA])smg;                     // [3][BM][SA]
    auto Bs = (uint32_t(*)[BN][SA])(smg + 3 * BM * SA);     // [3][BN][SA]

    const int z = blockIdx.z, zb = z / zdiv, zh = z % zdiv;
    const uint32_t* Ah = Ah_ + zb * sA1 + zh * sA2;
    const uint32_t* Al = Al_ + zb * sA1 + zh * sA2;
    const uint32_t* Bh = Bh_ + zb * sB1 + zh * sB2;
    const uint32_t* Bl = Bl_ + zb * sB1 + zh * sB2;

    const int tid = threadIdx.x;
    const int wid = tid >> 5, lane = tid & 31;
    const int gid = lane >> 2, tig = lane & 3;
    const int wm = wid % WARPS_M, wn = wid / WARPS_M;
    const int row0 = blockIdx.y * BM, col0 = blockIdx.x * BN;
    const int ldc2 = ldc >> 1;

    auto copyA = [&](int k0, int buf) {
#pragma unroll
        for (int i = 0; i < A_IT; i++) {
            int v = tid + i * THREADS;
            int r = v >> 2, q = v & 3;
            const uint32_t* src = (q < 2 ? Ah : Al)
                + (size_t)(row0 + r) * lda + (k0 >> 1) + (q & 1) * 4;
            cp16(&As[buf][r][(q & 1) * 4 + (q >> 1) * 8], src);
        }
    };
    auto copyB = [&](int k0, int buf) {
#pragma unroll
        for (int i = 0; i < B_IT; i++) {
            int v = tid + i * THREADS;
            int r = v >> 2, q = v & 3;
            const uint32_t* src = (q < 2 ? Bh : Bl)
                + (size_t)(col0 + r) * ldb + (k0 >> 1) + (q & 1) * 4;
            cp16(&Bs[buf][r][(q & 1) * 4 + (q >> 1) * 8], src);
        }
    };

    float acc[MF][NF][4];
#pragma unroll
    for (int mi = 0; mi < MF; mi++)
#pragma unroll
        for (int ni = 0; ni < NF; ni++)
#pragma unroll
            for (int q = 0; q < 4; q++) acc[mi][ni][q] = 0.f;

    const int nT = K / BK;
    copyA(0, 0); copyB(0, 0); CP_COMMIT();
    if (nT > 1) { copyA(BK, 1); copyB(BK, 1); }
    CP_COMMIT();

    for (int t = 0; t < nT; t++) {
        const int cur = t % 3;
        if (t + 2 < nT) {
            int nxt = (t + 2) % 3;
            copyA((t + 2) * BK, nxt);
            copyB((t + 2) * BK, nxt);
        }
        CP_COMMIT();
        cp_wait<2>();          // tile t resident
        __syncthreads();

        uint32_t ah[MF][4], al[MF][4];
#pragma unroll
        for (int mi = 0; mi < MF; mi++) {
            int m = wm * WM + mi * 16;
            ah[mi][0] = As[cur][m + gid    ][tig];
            ah[mi][1] = As[cur][m + gid + 8][tig];
            ah[mi][2] = As[cur][m + gid    ][tig + 4];
            ah[mi][3] = As[cur][m + gid + 8][tig + 4];
            al[mi][0] = As[cur][m + gid    ][tig + 8];
            al[mi][1] = As[cur][m + gid + 8][tig + 8];
            al[mi][2] = As[cur][m + gid    ][tig + 12];
            al[mi][3] = As[cur][m + gid + 8][tig + 12];
        }
#pragma unroll
        for (int nc = 0; nc < NF / NC; nc++) {
            uint32_t bh[NC][2], bl[NC][2];
#pragma unroll
            for (int nj = 0; nj < NC; nj++) {
                int n = wn * WN + (nc * NC + nj) * 8 + gid;
                bh[nj][0] = Bs[cur][n][tig];
                bh[nj][1] = Bs[cur][n][tig + 4];
                bl[nj][0] = Bs[cur][n][tig + 8];
                bl[nj][1] = Bs[cur][n][tig + 12];
            }
#pragma unroll
            for (int mi = 0; mi < MF; mi++)
#pragma unroll
                for (int nj = 0; nj < NC; nj++) {
                    float* c = acc[mi][nc * NC + nj];
                    mma_bf16(c, ah[mi], bh[nj]);
                    mma_bf16(c, ah[mi], bl[nj]);
                    mma_bf16(c, al[mi], bh[nj]);
                }
        }
        __syncthreads();
    }

    // ---- epilogue ----
    if constexpr (OMODE < 2) {
        float* Cf = (float*)C1 + zb * sC1 + zh * sC2;
#pragma unroll
        for (int mi = 0; mi < MF; mi++) {
            int r = row0 + wm * WM + mi * 16 + gid;
#pragma unroll
            for (int ni = 0; ni < NF; ni++) {
                int c = col0 + wn * WN + ni * 8 + tig * 2;
                float2 v01, v23;
                v01.x = acc[mi][ni][0]; v01.y = acc[mi][ni][1];
                v23.x = acc[mi][ni][2]; v23.y = acc[mi][ni][3];
                if (OMODE == 1) {
                    float b0 = bias[c], b1 = bias[c + 1];
                    v01.x += b0; v01.y += b1;
                    v23.x += b0; v23.y += b1;
                }
                *reinterpret_cast<float2*>(&Cf[(size_t)r * ldc + c])       = v01;
                *reinterpret_cast<float2*>(&Cf[(size_t)(r + 8) * ldc + c]) = v23;
            }
        }
    } else {
        uint32_t* Chp = (uint32_t*)C1 + ((zb * sC1 + zh * sC2) >> 1);
        uint32_t* Clp = (uint32_t*)C2 + ((zb * sC1 + zh * sC2) >> 1);
#pragma unroll
        for (int mi = 0; mi < MF; mi++) {
            int r = row0 + wm * WM + mi * 16 + gid;
#pragma unroll
            for (int ni = 0; ni < NF; ni++) {
                int c = col0 + wn * WN + ni * 8 + tig * 2;
                uint32_t h0, l0, h1, l1;
                split2(acc[mi][ni][0], acc[mi][ni][1], h0, l0);
                split2(acc[mi][ni][2], acc[mi][ni][3], h1, l1);
                Chp[(size_t)r * ldc2 + (c >> 1)]       = h0;
                Clp[(size_t)r * ldc2 + (c >> 1)]       = l0;
                Chp[(size_t)(r + 8) * ldc2 + (c >> 1)] = h1;
                Clp[(size_t)(r + 8) * ldc2 + (c >> 1)] = l1;
            }
        }
    }
}

// ---------------------------------------------------------------------------
// Fused flash attention: S = Q K^T * 0.125, online softmax, O = P V.
// Grid: (SEQ_N/128, BATCH*HEADS). 8 warps; warp w owns q-rows w*16..w*16+15
// and all 128 kv cols of each tile. V read from pre-transposed pair planes.
// ---------------------------------------------------------------------------
#define KROW 68
#define KT   (128 * KROW)          // 8704 u32 per K tile (hi+lo pairs)
#define VPL  (64 * 68)             // 4352 u32 per V^T plane
#define FBUF (KT + 2 * VPL)        // 17408 u32 per buffer
#define FLASH_SMEM (2 * FBUF * 4)  // 139264 bytes

__global__ __launch_bounds__(256, 1)
void flash_attn(const uint32_t* __restrict__ Qh, const uint32_t* __restrict__ Ql,
                const uint32_t* __restrict__ Kh, const uint32_t* __restrict__ Kl,
                const uint32_t* __restrict__ VTh, const uint32_t* __restrict__ VTl,
                uint32_t* __restrict__ Oh, uint32_t* __restrict__ Ol)
{
    extern __shared__ uint32_t sm[];

    const int tid = threadIdx.x;
    const int wid = tid >> 5, lane = tid & 31;
    const int gid = lane >> 2, tig = lane & 3;
    const int bh = blockIdx.y, b = bh >> 4, h = bh & 15;
    const int n0 = blockIdx.x * 128;

    const size_t qrow0 = (size_t)b * SEQ_N + n0;
    const size_t krow0 = (size_t)b * SEQ_M;
    const size_t vtrow0 = (size_t)bh * 64;     // V^T rows for this (b,h)
    const int hp = h * 32;                      // pair col offset (DHEAD/2)

    auto copyTile = [&](int tt, int buf) {
        uint32_t* smK = sm + buf * FBUF;
        uint32_t* smV = sm + buf * FBUF + KT;
        int m0 = tt * 128;
#pragma unroll
        for (int i = 0; i < 8; i++) {
            int v = tid + i * 256;
            int r = v >> 4, q = v & 15;
            const uint32_t* src = (q < 8 ? Kh : Kl)
                + (krow0 + m0 + r) * 512 + hp + (q & 7) * 4;
            cp16(&smK[r * KROW + (q >= 8 ? 32 : 0) + (q & 7) * 4], src);
        }
        // V^T: 2 planes x 64 d-rows x 16 chunks of 16B (64 kv-pairs per row)
#pragma unroll
        for (int i = 0; i < 8; i++) {
            int v = tid + i * 256;
            int pl = v >> 10, r = (v >> 4) & 63, c = v & 15;
            const uint32_t* src = (pl ? VTl : VTh)
                + (vtrow0 + r) * 512 + tt * 64 + c * 4;
            cp16(&smV[pl * VPL + r * 68 + c * 4], src);
        }
    };

    // Q fragments (held in registers for the whole CTA)
    uint32_t qh[4][4], ql[4][4];
    {
        size_t r0 = (qrow0 + wid * 16 + gid) * 512 + hp;
        size_t r8 = r0 + 8 * 512;
#pragma unroll
        for (int c = 0; c < 4; c++) {
            qh[c][0] = Qh[r0 + c * 8 + tig];
            qh[c][1] = Qh[r8 + c * 8 + tig];
            qh[c][2] = Qh[r0 + c * 8 + tig + 4];
            qh[c][3] = Qh[r8 + c * 8 + tig + 4];
            ql[c][0] = Ql[r0 + c * 8 + tig];
            ql[c][1] = Ql[r8 + c * 8 + tig];
            ql[c][2] = Ql[r0 + c * 8 + tig + 4];
            ql[c][3] = Ql[r8 + c * 8 + tig + 4];
        }
    }

    float o[8][4];
#pragma unroll
    for (int nj = 0; nj < 8; nj++)
#pragma unroll
        for (int q = 0; q < 4; q++) o[nj][q] = 0.f;
    float m0r = -1e30f, m1r = -1e30f;
    float l0r = 0.f, l1r = 0.f;

    copyTile(0, 0); CP_COMMIT();

    for (int tt = 0; tt < 8; tt++) {
        const int cur = tt & 1;
        if (tt < 7) { copyTile(tt + 1, cur ^ 1); CP_COMMIT(); cp_wait<1>(); }
        else        { cp_wait<0>(); }
        __syncthreads();

        const uint32_t* smK = sm + cur * FBUF;
        const uint32_t* smV = sm + cur * FBUF + KT;

        // ---- S = Q K^T ----
        float s[16][4];
#pragma unroll
        for (int nj = 0; nj < 16; nj++)
#pragma unroll
            for (int q = 0; q < 4; q++) s[nj][q] = 0.f;
#pragma unroll
        for (int nj = 0; nj < 16; nj++) {
            const uint32_t* kr = smK + (nj * 8 + gid) * KROW;
#pragma unroll
            for (int c = 0; c < 4; c++) {
                uint32_t kh2[2] = { kr[c * 8 + tig],      kr[c * 8 + tig + 4] };
                uint32_t kl2[2] = { kr[32 + c * 8 + tig], kr[32 + c * 8 + tig + 4] };
                mma_bf16(s[nj], qh[c], kh2);
                mma_bf16(s[nj], qh[c], kl2);
                mma_bf16(s[nj], ql[c], kh2);
            }
        }

        // ---- online softmax (rows gid and gid+8; quad = lanes sharing gid) ----
        float mt0 = -1e30f, mt1 = -1e30f;
#pragma unroll
        for (int nj = 0; nj < 16; nj++) {
            mt0 = fmaxf(mt0, fmaxf(s[nj][0], s[nj][1]));
            mt1 = fmaxf(mt1, fmaxf(s[nj][2], s[nj][3]));
        }
        mt0 = fmaxf(mt0, __shfl_xor_sync(0xffffffffu, mt0, 1));
        mt0 = fmaxf(mt0, __shfl_xor_sync(0xffffffffu, mt0, 2));
        mt1 = fmaxf(mt1, __shfl_xor_sync(0xffffffffu, mt1, 1));
        mt1 = fmaxf(mt1, __shfl_xor_sync(0xffffffffu, mt1, 2));
        float mn0 = fmaxf(m0r, mt0), mn1 = fmaxf(m1r, mt1);
        float a0 = __expf(0.125f * (m0r - mn0));
        float a1 = __expf(0.125f * (m1r - mn1));
        m0r = mn0; m1r = mn1;
        float ms0 = 0.125f * mn0, ms1 = 0.125f * mn1;
        float sum0 = 0.f, sum1 = 0.f;
#pragma unroll
        for (int nj = 0; nj < 16; nj++) {
            s[nj][0] = __expf(fmaf(s[nj][0], 0.125f, -ms0));
            s[nj][1] = __expf(fmaf(s[nj][1], 0.125f, -ms0));
            s[nj][2] = __expf(fmaf(s[nj][2], 0.125f, -ms1));
            s[nj][3] = __expf(fmaf(s[nj][3], 0.125f, -ms1));
            sum0 += s[nj][0] + s[nj][1];
            sum1 += s[nj][2] + s[nj][3];
        }
        sum0 += __shfl_xor_sync(0xffffffffu, sum0, 1);
        sum0 += __shfl_xor_sync(0xffffffffu, sum0, 2);
        sum1 += __shfl_xor_sync(0xffffffffu, sum1, 1);
        sum1 += __shfl_xor_sync(0xffffffffu, sum1, 2);
        l0r = l0r * a0 + sum0;
        l1r = l1r * a1 + sum1;
#pragma unroll
        for (int nj = 0; nj < 8; nj++) {
            o[nj][0] *= a0; o[nj][1] *= a0;
            o[nj][2] *= a1; o[nj][3] *= a1;
        }

        // ---- O += P V (P split in-register; V^T fragments = clean u32 loads) ----
#pragma unroll
        for (int kc = 0; kc < 8; kc++) {
            uint32_t ph[4], pl[4];
            split2(s[2 * kc][0],     s[2 * kc][1],     ph[0], pl[0]);
            split2(s[2 * kc][2],     s[2 * kc][3],     ph[1], pl[1]);
            split2(s[2 * kc + 1][0], s[2 * kc + 1][1], ph[2], pl[2]);
            split2(s[2 * kc + 1][2], s[2 * kc + 1][3], ph[3], pl[3]);
#pragma unroll
            for (int nj = 0; nj < 8; nj++) {
                int n = nj * 8 + gid;                 // dhead column
                const uint32_t* vrh = smV + n * 68;
                const uint32_t* vrl = vrh + VPL;
                uint32_t vh2[2] = { vrh[kc * 8 + tig], vrh[kc * 8 + tig + 4] };
                uint32_t vl2[2] = { vrl[kc * 8 + tig], vrl[kc * 8 + tig + 4] };
                mma_bf16(o[nj], ph, vh2);
                mma_bf16(o[nj], ph, vl2);
                mma_bf16(o[nj], pl, vh2);
            }
        }
        __syncthreads();
    }

    // ---- epilogue: O /= l, write split pairs ----
    float i0 = 1.f / l0r, i1 = 1.f / l1r;
    size_t r0 = (qrow0 + wid * 16 + gid) * 512 + hp;
    size_t r8 = r0 + 8 * 512;
#pragma unroll
    for (int nj = 0; nj < 8; nj++) {
        uint32_t hh, ll;
        split2(o[nj][0] * i0, o[nj][1] * i0, hh, ll);
        Oh[r0 + nj * 4 + tig] = hh;  Ol[r0 + nj * 4 + tig] = ll;
        split2(o[nj][2] * i1, o[nj][3] * i1, hh, ll);
        Oh[r8 + nj * 4 + tig] = hh;  Ol[r8 + nj * 4 + tig] = ll;
    }
}

// ---------------------------------------------------------------------------
extern "C" void kernel_launch(void* const* d_in, const int* in_sizes, int n_in,
                              void* d_out, int out_size)
{
    const float* x   = (const float*)d_in[0];
    const float* ctx = (const float*)d_in[1];
    const float* Wq  = (const float*)d_in[2];
    const float* Wk  = (const float*)d_in[3];
    const float* Wv  = (const float*)d_in[4];
    const float* Wo  = (const float*)d_in[5];
    const float* bo  = (const float*)d_in[6];
    float* out = (float*)d_out;

    uint32_t *Xh, *Xl, *Ch, *Cl, *Wqh, *Wql, *Wkh, *Wkl, *Wvh, *Wvl, *Woh, *Wol;
    uint32_t *Qh, *Ql, *Kh, *Kl, *VTh, *VTl, *Oh, *Ol;
    float *Vf;
    cudaGetSymbolAddress((void**)&Xh, g_x_hi);  cudaGetSymbolAddress((void**)&Xl, g_x_lo);
    cudaGetSymbolAddress((void**)&Ch, g_c_hi);  cudaGetSymbolAddress((void**)&Cl, g_c_lo);
    cudaGetSymbolAddress((void**)&Wqh, g_Wq_hi); cudaGetSymbolAddress((void**)&Wql, g_Wq_lo);
    cudaGetSymbolAddress((void**)&Wkh, g_Wk_hi); cudaGetSymbolAddress((void**)&Wkl, g_Wk_lo);
    cudaGetSymbolAddress((void**)&Wvh, g_Wv_hi); cudaGetSymbolAddress((void**)&Wvl, g_Wv_lo);
    cudaGetSymbolAddress((void**)&Woh, g_Wo_hi); cudaGetSymbolAddress((void**)&Wol, g_Wo_lo);
    cudaGetSymbolAddress((void**)&Qh, g_Q_hi);  cudaGetSymbolAddress((void**)&Ql, g_Q_lo);
    cudaGetSymbolAddress((void**)&Kh, g_K_hi);  cudaGetSymbolAddress((void**)&Kl, g_K_lo);
    cudaGetSymbolAddress((void**)&VTh, g_VT_hi); cudaGetSymbolAddress((void**)&VTl, g_VT_lo);
    cudaGetSymbolAddress((void**)&Oh, g_O_hi);  cudaGetSymbolAddress((void**)&Ol, g_O_lo);
    cudaGetSymbolAddress((void**)&Vf, g_Vf);

    cudaFuncSetAttribute(flash_attn, cudaFuncAttributeMaxDynamicSharedMemorySize,
                         FLASH_SMEM);
    cudaFuncSetAttribute(mma_gemm<32,64,0>, cudaFuncAttributeMaxDynamicSharedMemorySize,
                         GEMM_SMEM);
    cudaFuncSetAttribute(mma_gemm<32,64,1>, cudaFuncAttributeMaxDynamicSharedMemorySize,
                         GEMM_SMEM);
    cudaFuncSetAttribute(mma_gemm<32,64,2>, cudaFuncAttributeMaxDynamicSharedMemorySize,
                         GEMM_SMEM);

    // ---- pre-split inputs ----
    split_pairs<<<(unsigned)((size_t)ROWS_Q * QDIM / 2 / 256), 256>>>(
        (const float2*)x, Xh, Xl, (size_t)ROWS_Q * QDIM / 2);
    split_pairs<<<(unsigned)((size_t)ROWS_KV * CDIM / 2 / 256), 256>>>(
        (const float2*)ctx, Ch, Cl, (size_t)ROWS_KV * CDIM / 2);
    split_transpose<<<dim3(INNER / 32, QDIM / 32, 1), 256>>>(Wq, Wqh, Wql, QDIM, INNER);
    split_transpose<<<dim3(INNER / 32, CDIM / 32, 1), 256>>>(Wk, Wkh, Wkl, CDIM, INNER);
    split_transpose<<<dim3(INNER / 32, CDIM / 32, 1), 256>>>(Wv, Wvh, Wvl, CDIM, INNER);
    split_transpose<<<dim3(QDIM / 32, INNER / 32, 1), 256>>>(Wo, Woh, Wol, INNER, QDIM);

    // 1) Q = x @ Wq -> split
    mma_gemm<32,64,2><<<dim3(INNER/128, ROWS_Q/128, 1), 256, GEMM_SMEM>>>(
        Xh, Xl, Wqh, Wql, Qh, Ql, nullptr,
        QDIM, QDIM/2, QDIM/2, INNER, 1, 0,0, 0,0, 0,0);

    // 2) K = ctx @ Wk -> split
    mma_gemm<32,64,2><<<dim3(INNER/128, ROWS_KV/128, 1), 256, GEMM_SMEM>>>(
        Ch, Cl, Wkh, Wkl, Kh, Kl, nullptr,
        CDIM, CDIM/2, CDIM/2, INNER, 1, 0,0, 0,0, 0,0);

    // 3) V = ctx @ Wv -> f32, then batched transpose-split to V^T pairs
    mma_gemm<32,64,0><<<dim3(INNER/128, ROWS_KV/128, 1), 256, GEMM_SMEM>>>(
        Ch, Cl, Wvh, Wvl, Vf, nullptr, nullptr,
        CDIM, CDIM/2, CDIM/2, INNER, 1, 0,0, 0,0, 0,0);
    split_transpose<<<dim3(INNER / 32, SEQ_M / 32, BATCH), 256>>>(
        Vf, VTh, VTl, SEQ_M, INNER);

    // 4-6) fused flash attention -> split O
    flash_attn<<<dim3(SEQ_N/128, BATCH*HEADS), 256, FLASH_SMEM>>>(
        Qh, Ql, Kh, Kl, VTh, VTl, Oh, Ol);

    // 7) out = O @ Wo + bo -> f32
    mma_gemm<32,64,1><<<dim3(QDIM/128, ROWS_Q/128, 1), 256, GEMM_SMEM>>>(
        Oh, Ol, Woh, Wol, out, nullptr, bo,
        INNER, INNER/2, INNER/2, QDIM, 1, 0,0, 0,0, 0,0);
}